// round 1
// baseline (speedup 1.0000x reference)
#include <cuda_runtime.h>
#include <cstdint>

#define NN 100000
#define NE 1600000
#define FDIM 128
#define NCLS 40

// Scratch (device globals: allocation-free per harness rules)
__device__ float g_m[(size_t)NN * FDIM];    // pool output (messages)
__device__ float g_agg[(size_t)NN * FDIM];  // segment-max aggregate
__device__ float g_h[(size_t)NN * FDIM];    // layer-1 hidden

#define FMA2(acc, a, b) asm("fma.rn.f32x2 %0, %1, %2, %0;" : "+l"(acc) : "l"(a), "l"(b))

// out[i][j] = act( X[i,:]·W0[j,:] + (A? A[i,:]·W1[j,:] :0) + b0[j] + (b1? b1[j] :0) )
// X,A: [n,128] row-major. W: [fout,128] row-major. out: [n,fout]. fout % 4 == 0, fout <= 128.
// Tile: 64 rows x 128 cols per block; 256 threads; thread = 8 rows x 4 cols.
__global__ void __launch_bounds__(256) dual_gemm_kernel(
    const float* __restrict__ X, const float* __restrict__ A,
    const float* __restrict__ W0, const float* __restrict__ W1,
    const float* __restrict__ b0, const float* __restrict__ b1,
    float* __restrict__ out, int n, int fout, int do_relu)
{
    // X tile stored DUPLICATED ({v,v} pairs) so compute reads packed b64 broadcasts.
    __shared__ __align__(16) float xs[64][66];   // [row][2*k {lo,hi same}], 32 k per chunk
    __shared__ __align__(16) float ws[32][132];  // [k][col], padded

    const int tid  = threadIdx.x;
    const int lane = tid & 31;
    const int wrp  = tid >> 5;      // 0..7 -> rows wrp*8 .. wrp*8+7
    const int row0 = blockIdx.x * 64;

    unsigned long long acc01[8], acc23[8];      // packed f32x2 accumulators (cols c,c+1 | c+2,c+3)
    #pragma unroll
    for (int r = 0; r < 8; r++) { acc01[r] = 0ull; acc23[r] = 0ull; }

    const int npass = (A != nullptr) ? 2 : 1;
    for (int pass = 0; pass < npass; pass++) {
        const float* __restrict__ Xp = pass ? A  : X;
        const float* __restrict__ Wp = pass ? W1 : W0;
        for (int kc = 0; kc < 128; kc += 32) {
            __syncthreads();
            // ---- X tile: 64 rows x 32 k = 512 float4 loads, 2 per thread ----
            #pragma unroll
            for (int i = 0; i < 2; i++) {
                int f  = tid + i * 256;       // 0..511
                int r  = f >> 3;              // 0..63
                int k4 = f & 7;               // 0..7
                float4 v = make_float4(0.f, 0.f, 0.f, 0.f);
                int gr = row0 + r;
                if (gr < n) v = *(const float4*)(Xp + (size_t)gr * 128 + kc + k4 * 4);
                int kb = (k4 * 4) * 2;
                *(float2*)&xs[r][kb + 0] = make_float2(v.x, v.x);
                *(float2*)&xs[r][kb + 2] = make_float2(v.y, v.y);
                *(float2*)&xs[r][kb + 4] = make_float2(v.z, v.z);
                *(float2*)&xs[r][kb + 6] = make_float2(v.w, v.w);
            }
            // ---- W tile: 128 cols x 32 k = 1024 float4 loads, 4 per thread; store k-major ----
            #pragma unroll
            for (int i = 0; i < 4; i++) {
                int f  = tid + i * 256;       // 0..1023
                int c  = f >> 3;              // 0..127
                int k4 = f & 7;
                float4 v = make_float4(0.f, 0.f, 0.f, 0.f);
                if (c < fout) v = *(const float4*)(Wp + (size_t)c * 128 + kc + k4 * 4);
                ws[k4 * 4 + 0][c] = v.x;
                ws[k4 * 4 + 1][c] = v.y;
                ws[k4 * 4 + 2][c] = v.z;
                ws[k4 * 4 + 3][c] = v.w;
            }
            __syncthreads();
            // ---- compute: per k: 1 LDS.128 (W) + 8 LDS.64 (X bcast) + 16 FFMA2 ----
            #pragma unroll 4
            for (int kk = 0; kk < 32; kk++) {
                ulonglong2 wv = *(const ulonglong2*)&ws[kk][lane * 4];
                #pragma unroll
                for (int r = 0; r < 8; r++) {
                    unsigned long long xv =
                        *(const unsigned long long*)&xs[wrp * 8 + r][kk * 2];
                    FMA2(acc01[r], xv, wv.x);
                    FMA2(acc23[r], xv, wv.y);
                }
            }
        }
    }

    // ---- epilogue ----
    int col = lane * 4;
    if (col >= fout) return;
    float bx = b0[col + 0], by = b0[col + 1], bz = b0[col + 2], bw = b0[col + 3];
    if (b1 != nullptr) { bx += b1[col + 0]; by += b1[col + 1]; bz += b1[col + 2]; bw += b1[col + 3]; }
    #pragma unroll
    for (int r = 0; r < 8; r++) {
        int gr = row0 + wrp * 8 + r;
        if (gr >= n) continue;
        uint32_t l0, h0, l1, h1;
        asm("mov.b64 {%0,%1}, %2;" : "=r"(l0), "=r"(h0) : "l"(acc01[r]));
        asm("mov.b64 {%0,%1}, %2;" : "=r"(l1), "=r"(h1) : "l"(acc23[r]));
        float4 o;
        o.x = __uint_as_float(l0) + bx;
        o.y = __uint_as_float(h0) + by;
        o.z = __uint_as_float(l1) + bz;
        o.w = __uint_as_float(h1) + bw;
        if (do_relu) {
            o.x = fmaxf(o.x, 0.f); o.y = fmaxf(o.y, 0.f);
            o.z = fmaxf(o.z, 0.f); o.w = fmaxf(o.w, 0.f);
        }
        *(float4*)(out + (size_t)gr * fout + col) = o;
    }
}

__global__ void zero_kernel(float4* __restrict__ p, int n4)
{
    int i = blockIdx.x * blockDim.x + threadIdx.x;
    if (i < n4) p[i] = make_float4(0.f, 0.f, 0.f, 0.f);
}

// Per-edge segment-max scatter. One warp per edge: 32 lanes x float4 = 128 feats.
// Messages are >= 0 (post-ReLU) so int atomicMax on the bit pattern is exact,
// and v == 0 never beats the 0-init -> skip those atomics entirely.
__global__ void __launch_bounds__(256) edge_max_kernel(
    const int* __restrict__ src, const int* __restrict__ dst,
    const float* __restrict__ m, int* __restrict__ agg)
{
    int e = blockIdx.x * 8 + (threadIdx.x >> 5);
    if (e >= NE) return;
    int lane = threadIdx.x & 31;
    int s = __ldg(&src[e]);
    int d = __ldg(&dst[e]);
    float4 v = *(const float4*)(m + (size_t)s * FDIM + lane * 4);
    int* a = agg + (size_t)d * FDIM + lane * 4;
    if (v.x > 0.f) atomicMax(a + 0, __float_as_int(v.x));
    if (v.y > 0.f) atomicMax(a + 1, __float_as_int(v.y));
    if (v.z > 0.f) atomicMax(a + 2, __float_as_int(v.z));
    if (v.w > 0.f) atomicMax(a + 3, __float_as_int(v.w));
}

extern "C" void kernel_launch(void* const* d_in, const int* in_sizes, int n_in,
                              void* d_out, int out_size)
{
    const float* in_feat  = (const float*)d_in[0];
    const int*   src      = (const int*)  d_in[1];
    const int*   dst      = (const int*)  d_in[2];
    const float* pool_w1  = (const float*)d_in[3];
    const float* pool_b1  = (const float*)d_in[4];
    const float* self_w1  = (const float*)d_in[5];
    const float* self_b1  = (const float*)d_in[6];
    const float* neigh_w1 = (const float*)d_in[7];
    const float* neigh_b1 = (const float*)d_in[8];
    const float* pool_w2  = (const float*)d_in[9];
    const float* pool_b2  = (const float*)d_in[10];
    const float* self_w2  = (const float*)d_in[11];
    const float* self_b2  = (const float*)d_in[12];
    const float* neigh_w2 = (const float*)d_in[13];
    const float* neigh_b2 = (const float*)d_in[14];

    float *m, *agg, *h;
    cudaGetSymbolAddress((void**)&m,   g_m);
    cudaGetSymbolAddress((void**)&agg, g_agg);
    cudaGetSymbolAddress((void**)&h,   g_h);

    const int ggrid = (NN + 63) / 64;
    const int nz4   = NN * FDIM / 4;
    const int zgrid = (nz4 + 255) / 256;
    const int egrid = NE / 8;

    // ---- layer 1 ----
    dual_gemm_kernel<<<ggrid, 256>>>(in_feat, nullptr, pool_w1, nullptr,
                                     pool_b1, nullptr, m, NN, FDIM, 1);
    zero_kernel<<<zgrid, 256>>>((float4*)agg, nz4);
    edge_max_kernel<<<egrid, 256>>>(src, dst, m, (int*)agg);
    dual_gemm_kernel<<<ggrid, 256>>>(in_feat, agg, self_w1, neigh_w1,
                                     self_b1, neigh_b1, h, NN, FDIM, 1);
    // ---- layer 2 ----
    dual_gemm_kernel<<<ggrid, 256>>>(h, nullptr, pool_w2, nullptr,
                                     pool_b2, nullptr, m, NN, FDIM, 1);
    zero_kernel<<<zgrid, 256>>>((float4*)agg, nz4);
    edge_max_kernel<<<egrid, 256>>>(src, dst, m, (int*)agg);
    dual_gemm_kernel<<<ggrid, 256>>>(h, agg, self_w2, neigh_w2,
                                     self_b2, neigh_b2, (float*)d_out, NN, NCLS, 0);
}

// round 2
// speedup vs baseline: 1.1430x; 1.1430x over previous
#include <cuda_runtime.h>
#include <cstdint>

#define NN 100000
#define NE 1600000
#define FDIM 128
#define NCLS 40

typedef unsigned long long u64;

// Scratch (device globals: allocation-free per harness rules)
__device__ float g_m[(size_t)NN * FDIM];    // pool output (messages)
__device__ float g_agg[(size_t)NN * FDIM];  // segment-max aggregate
__device__ float g_h[(size_t)NN * FDIM];    // layer-1 hidden

#define FMA2(acc, a, b) asm("fma.rn.f32x2 %0, %1, %2, %0;" : "+l"(acc) : "l"(a), "l"(b))
#define PACK2(d, s)     asm("mov.b64 %0, {%1, %1};" : "=l"(d) : "r"(s))
#define UNPK(lo, hi, s) asm("mov.b64 {%0, %1}, %2;" : "=r"(lo), "=r"(hi) : "l"(s))

// swizzled col index for ws: insert a 4-float gap every 32 cols (bank decorrelation)
__device__ __forceinline__ int wsi(int c) { return c + ((c >> 5) << 2); }

// out[i][j] = act( X[i,:]·W0[j,:] + (A? A[i,:]·W1[j,:] :0) + b0[j] + (b1? b1[j] :0) )
// X,A: [n,128] rm. W: [fout,128] rm. Tile: 128 rows x (16*TC) cols, 256 threads,
// thread = 8 rows (4 f32x2 row-pairs) x TC cols. 1 B LDS per FMA.
template<int TC>
__global__ void __launch_bounds__(256, 2) gemm_kernel(
    const float* __restrict__ X, const float* __restrict__ A,
    const float* __restrict__ W0, const float* __restrict__ W1,
    const float* __restrict__ b0, const float* __restrict__ b1,
    float* __restrict__ out, int n, int fout, int do_relu)
{
    constexpr int BN = 16 * TC;
    __shared__ __align__(16) float xs[16][132];  // [k][row], k-chunk = 16
    __shared__ __align__(16) float ws[16][144];  // [k][swizzled col]

    const int tid = threadIdx.x;
    const int tx  = tid & 15;        // col group: cols tx*TC .. tx*TC+TC-1
    const int ty  = tid >> 4;        // row group: rows ty*8 .. ty*8+7
    const int row0 = blockIdx.x * 128;

    u64 acc[4][TC];                  // [row-pair][col], packed f32x2 over rows
    #pragma unroll
    for (int p = 0; p < 4; p++)
        #pragma unroll
        for (int c = 0; c < TC; c++) acc[p][c] = 0ull;

    const int npass = (A != nullptr) ? 2 : 1;
    for (int pass = 0; pass < npass; pass++) {
        const float* __restrict__ Xp = pass ? A  : X;
        const float* __restrict__ Wp = pass ? W1 : W0;
        for (int kc = 0; kc < 128; kc += 16) {
            __syncthreads();
            // ---- X tile fill: 128 rows x 16 k, transposed to [k][row].
            //      4 lanes cover one row's 64B contiguous -> coalesced. ----
            #pragma unroll
            for (int i = 0; i < 2; i++) {
                int f  = tid + i * 256;          // 0..511
                int r  = f >> 2;                 // 0..127
                int kq = f & 3;                  // 0..3 -> k = kq*4..+3
                float4 v = make_float4(0.f, 0.f, 0.f, 0.f);
                int gr = row0 + r;
                if (gr < n) v = *(const float4*)(Xp + (size_t)gr * 128 + kc + kq * 4);
                xs[kq * 4 + 0][r] = v.x;
                xs[kq * 4 + 1][r] = v.y;
                xs[kq * 4 + 2][r] = v.z;
                xs[kq * 4 + 3][r] = v.w;
            }
            // ---- W tile fill: BN cols x 16 k, transposed to [k][col] (swizzled) ----
            #pragma unroll
            for (int i = 0; i < BN / 64; i++) {
                int f  = tid + i * 256;          // 0..BN*4-1
                int c  = f & (BN - 1);
                int kq = f / BN;                 // 0..3
                float4 v = make_float4(0.f, 0.f, 0.f, 0.f);
                if (c < fout) v = *(const float4*)(Wp + (size_t)c * 128 + kc + kq * 4);
                int ci = wsi(c);
                ws[kq * 4 + 0][ci] = v.x;
                ws[kq * 4 + 1][ci] = v.y;
                ws[kq * 4 + 2][ci] = v.z;
                ws[kq * 4 + 3][ci] = v.w;
            }
            __syncthreads();
            // ---- compute: per k: 2 LDS.128 (X, broadcast) + TC/4 LDS.128 (W)
            //      + TC packs + 4*TC FFMA2 ----
            #pragma unroll
            for (int k = 0; k < 16; k++) {
                ulonglong2 xa = *(const ulonglong2*)&xs[k][ty * 8];
                ulonglong2 xb = *(const ulonglong2*)&xs[k][ty * 8 + 4];
                u64 xp[4] = { xa.x, xa.y, xb.x, xb.y };
                u64 wd[TC];
                #pragma unroll
                for (int c4 = 0; c4 < TC; c4 += 4) {
                    float4 w = *(const float4*)&ws[k][wsi(tx * TC + c4)];
                    PACK2(wd[c4 + 0], __float_as_uint(w.x));
                    PACK2(wd[c4 + 1], __float_as_uint(w.y));
                    PACK2(wd[c4 + 2], __float_as_uint(w.z));
                    PACK2(wd[c4 + 3], __float_as_uint(w.w));
                }
                #pragma unroll
                for (int p = 0; p < 4; p++)
                    #pragma unroll
                    for (int c = 0; c < TC; c++)
                        FMA2(acc[p][c], xp[p], wd[c]);
            }
        }
    }

    // ---- epilogue ----
    const int colb = tx * TC;
    float bias[TC];
    #pragma unroll
    for (int c = 0; c < TC; c++) {
        int col = colb + c;
        float bv = 0.f;
        if (col < fout) {
            bv = b0[col];
            if (b1 != nullptr) bv += b1[col];
        }
        bias[c] = bv;
    }
    #pragma unroll
    for (int p = 0; p < 4; p++) {
        int r0 = row0 + ty * 8 + 2 * p;
        float vlo[TC], vhi[TC];
        #pragma unroll
        for (int c = 0; c < TC; c++) {
            uint32_t lo, hi;
            UNPK(lo, hi, acc[p][c]);
            float a = __uint_as_float(lo) + bias[c];
            float b = __uint_as_float(hi) + bias[c];
            if (do_relu) { a = fmaxf(a, 0.f); b = fmaxf(b, 0.f); }
            vlo[c] = a; vhi[c] = b;
        }
        #pragma unroll
        for (int c4 = 0; c4 < TC; c4 += 4) {
            if (colb + c4 >= fout) continue;
            if (r0 < n)
                *(float4*)(out + (size_t)r0 * fout + colb + c4) =
                    make_float4(vlo[c4], vlo[c4 + 1], vlo[c4 + 2], vlo[c4 + 3]);
            if (r0 + 1 < n)
                *(float4*)(out + (size_t)(r0 + 1) * fout + colb + c4) =
                    make_float4(vhi[c4], vhi[c4 + 1], vhi[c4 + 2], vhi[c4 + 3]);
        }
    }
}

// Per-edge segment-max scatter. One warp per edge: 32 lanes x float4 = 128 feats.
// Messages are >= 0 (post-ReLU) so int atomicMax on the bit pattern is exact,
// and v == 0 never beats the 0-init -> skip those atomics entirely.
__global__ void __launch_bounds__(256) edge_max_kernel(
    const int* __restrict__ src, const int* __restrict__ dst,
    const float* __restrict__ m, int* __restrict__ agg)
{
    int e = blockIdx.x * 8 + (threadIdx.x >> 5);
    if (e >= NE) return;
    int lane = threadIdx.x & 31;
    int s = __ldg(&src[e]);
    int d = __ldg(&dst[e]);
    float4 v = *(const float4*)(m + (size_t)s * FDIM + lane * 4);
    int* a = agg + (size_t)d * FDIM + lane * 4;
    if (v.x > 0.f) atomicMax(a + 0, __float_as_int(v.x));
    if (v.y > 0.f) atomicMax(a + 1, __float_as_int(v.y));
    if (v.z > 0.f) atomicMax(a + 2, __float_as_int(v.z));
    if (v.w > 0.f) atomicMax(a + 3, __float_as_int(v.w));
}

extern "C" void kernel_launch(void* const* d_in, const int* in_sizes, int n_in,
                              void* d_out, int out_size)
{
    const float* in_feat  = (const float*)d_in[0];
    const int*   src      = (const int*)  d_in[1];
    const int*   dst      = (const int*)  d_in[2];
    const float* pool_w1  = (const float*)d_in[3];
    const float* pool_b1  = (const float*)d_in[4];
    const float* self_w1  = (const float*)d_in[5];
    const float* self_b1  = (const float*)d_in[6];
    const float* neigh_w1 = (const float*)d_in[7];
    const float* neigh_b1 = (const float*)d_in[8];
    const float* pool_w2  = (const float*)d_in[9];
    const float* pool_b2  = (const float*)d_in[10];
    const float* self_w2  = (const float*)d_in[11];
    const float* self_b2  = (const float*)d_in[12];
    const float* neigh_w2 = (const float*)d_in[13];
    const float* neigh_b2 = (const float*)d_in[14];

    float *m, *agg, *h;
    cudaGetSymbolAddress((void**)&m,   g_m);
    cudaGetSymbolAddress((void**)&agg, g_agg);
    cudaGetSymbolAddress((void**)&h,   g_h);

    const int ggrid = (NN + 127) / 128;
    const int egrid = NE / 8;
    const size_t abytes = (size_t)NN * FDIM * sizeof(float);

    // ---- layer 1 ----
    gemm_kernel<8><<<ggrid, 256>>>(in_feat, nullptr, pool_w1, nullptr,
                                   pool_b1, nullptr, m, NN, FDIM, 1);
    cudaMemsetAsync(agg, 0, abytes);
    edge_max_kernel<<<egrid, 256>>>(src, dst, m, (int*)agg);
    gemm_kernel<8><<<ggrid, 256>>>(in_feat, agg, self_w1, neigh_w1,
                                   self_b1, neigh_b1, h, NN, FDIM, 1);
    // ---- layer 2 ----
    gemm_kernel<8><<<ggrid, 256>>>(h, nullptr, pool_w2, nullptr,
                                   pool_b2, nullptr, m, NN, FDIM, 1);
    cudaMemsetAsync(agg, 0, abytes);
    edge_max_kernel<<<egrid, 256>>>(src, dst, m, (int*)agg);
    gemm_kernel<4><<<ggrid, 256>>>(h, agg, self_w2, neigh_w2,
                                   self_b2, neigh_b2, (float*)d_out, NN, NCLS, 0);
}

// round 3
// speedup vs baseline: 1.9195x; 1.6794x over previous
#include <cuda_runtime.h>
#include <cstdint>

#define NN 100000
#define NE 1600000
#define FDIM 128
#define NCLS 40

typedef unsigned long long u64;

// Scratch (device globals: allocation-free per harness rules)
__device__ float g_m[(size_t)NN * FDIM];    // pool output (messages)
__device__ float g_agg[(size_t)NN * FDIM];  // segment-max aggregate
__device__ float g_h[(size_t)NN * FDIM];    // layer-1 hidden
__device__ int   g_deg[NN];                 // in-degree histogram
__device__ int   g_off[NN + 1];             // CSR row offsets (by dst)
__device__ int   g_pos[NN];                 // scatter cursors
__device__ int   g_csr[NE];                 // src ids grouped by dst

#define FMA2(acc, a, b) asm("fma.rn.f32x2 %0, %1, %2, %0;" : "+l"(acc) : "l"(a), "l"(b))
#define PACK2(d, s)     asm("mov.b64 %0, {%1, %1};" : "=l"(d) : "r"(s))
#define UNPK(lo, hi, s) asm("mov.b64 {%0, %1}, %2;" : "=r"(lo), "=r"(hi) : "l"(s))

// swizzled col index for ws: insert a 4-float gap every 32 cols (bank decorrelation)
__device__ __forceinline__ int wsi(int c) { return c + ((c >> 5) << 2); }

// ======================= GEMM (software-pipelined) ==========================
// out[i][j] = act( X[i,:]·W0[j,:] + (A? A[i,:]·W1[j,:] :0) + b0[j] + (b1? b1[j] :0) )
// Tile: 128 rows x (16*TC) cols, 256 threads, thread = 8 rows x TC cols.
// Double-buffered smem, register prefetch, ONE sync per 16-k chunk.
template<int TC>
__global__ void __launch_bounds__(256, 2) gemm_kernel(
    const float* __restrict__ X, const float* __restrict__ A,
    const float* __restrict__ W0, const float* __restrict__ W1,
    const float* __restrict__ b0, const float* __restrict__ b1,
    float* __restrict__ out, int n, int fout, int do_relu)
{
    constexpr int BN = 16 * TC;
    constexpr int NW4 = BN / 64;                 // W prefetch float4s per thread
    __shared__ __align__(16) float xs[2][16][132];  // [buf][k][row]
    __shared__ __align__(16) float ws[2][16][144];  // [buf][k][swizzled col]

    const int tid = threadIdx.x;
    const int tx  = tid & 15;
    const int ty  = tid >> 4;
    const int row0 = blockIdx.x * 128;
    const int nch = (A != nullptr) ? 16 : 8;     // 16-k chunks (8 per pass)

    u64 acc[4][TC];
    #pragma unroll
    for (int p = 0; p < 4; p++)
        #pragma unroll
        for (int c = 0; c < TC; c++) acc[p][c] = 0ull;

    float4 xr[2], wr[NW4];

    // --- register prefetch of chunk `idx` ---
    auto load_chunk = [&](int idx) {
        const float* __restrict__ Xp = (idx < 8) ? X  : A;
        const float* __restrict__ Wp = (idx < 8) ? W0 : W1;
        const int kc = (idx & 7) * 16;
        #pragma unroll
        for (int i = 0; i < 2; i++) {
            int f = tid + i * 256;               // 0..511
            int r = f >> 2, kq = f & 3;
            int gr = row0 + r;
            xr[i] = make_float4(0.f, 0.f, 0.f, 0.f);
            if (gr < n) xr[i] = *(const float4*)(Xp + (size_t)gr * 128 + kc + kq * 4);
        }
        #pragma unroll
        for (int i = 0; i < NW4; i++) {
            int f = tid + i * 256;               // 0..BN*4-1
            int c = f & (BN - 1), kq = f / BN;
            wr[i] = make_float4(0.f, 0.f, 0.f, 0.f);
            if (c < fout) wr[i] = *(const float4*)(Wp + (size_t)c * 128 + kc + kq * 4);
        }
    };
    // --- store prefetched regs into smem buffer `b` ---
    auto store_chunk = [&](int b) {
        #pragma unroll
        for (int i = 0; i < 2; i++) {
            int f = tid + i * 256;
            int r = f >> 2, kq = f & 3;
            xs[b][kq * 4 + 0][r] = xr[i].x;
            xs[b][kq * 4 + 1][r] = xr[i].y;
            xs[b][kq * 4 + 2][r] = xr[i].z;
            xs[b][kq * 4 + 3][r] = xr[i].w;
        }
        #pragma unroll
        for (int i = 0; i < NW4; i++) {
            int f = tid + i * 256;
            int c = f & (BN - 1), kq = f / BN;
            int ci = wsi(c);
            ws[b][kq * 4 + 0][ci] = wr[i].x;
            ws[b][kq * 4 + 1][ci] = wr[i].y;
            ws[b][kq * 4 + 2][ci] = wr[i].z;
            ws[b][kq * 4 + 3][ci] = wr[i].w;
        }
    };

    // prolog: chunk0 -> buf0; prefetch chunk1 into regs
    load_chunk(0);
    store_chunk(0);
    load_chunk(1);
    __syncthreads();

    for (int c = 0; c < nch; c++) {
        const int cur = c & 1;
        // stash chunk c+1 (already in regs) into the other buffer, start load c+2
        if (c + 1 < nch) {
            store_chunk(cur ^ 1);
            if (c + 2 < nch) load_chunk(c + 2);
        }
        // compute on buffer `cur`
        #pragma unroll
        for (int k = 0; k < 16; k++) {
            ulonglong2 xa = *(const ulonglong2*)&xs[cur][k][ty * 8];
            ulonglong2 xb = *(const ulonglong2*)&xs[cur][k][ty * 8 + 4];
            u64 xp[4] = { xa.x, xa.y, xb.x, xb.y };
            u64 wd[TC];
            #pragma unroll
            for (int c4 = 0; c4 < TC; c4 += 4) {
                float4 w = *(const float4*)&ws[cur][k][wsi(tx * TC + c4)];
                PACK2(wd[c4 + 0], __float_as_uint(w.x));
                PACK2(wd[c4 + 1], __float_as_uint(w.y));
                PACK2(wd[c4 + 2], __float_as_uint(w.z));
                PACK2(wd[c4 + 3], __float_as_uint(w.w));
            }
            #pragma unroll
            for (int p = 0; p < 4; p++)
                #pragma unroll
                for (int cc = 0; cc < TC; cc++)
                    FMA2(acc[p][cc], xp[p], wd[cc]);
        }
        __syncthreads();
    }

    // ---- epilogue ----
    const int colb = tx * TC;
    float bias[TC];
    #pragma unroll
    for (int c = 0; c < TC; c++) {
        int col = colb + c;
        float bv = 0.f;
        if (col < fout) {
            bv = b0[col];
            if (b1 != nullptr) bv += b1[col];
        }
        bias[c] = bv;
    }
    #pragma unroll
    for (int p = 0; p < 4; p++) {
        int r0 = row0 + ty * 8 + 2 * p;
        float vlo[TC], vhi[TC];
        #pragma unroll
        for (int c = 0; c < TC; c++) {
            uint32_t lo, hi;
            UNPK(lo, hi, acc[p][c]);
            float a = __uint_as_float(lo) + bias[c];
            float b = __uint_as_float(hi) + bias[c];
            if (do_relu) { a = fmaxf(a, 0.f); b = fmaxf(b, 0.f); }
            vlo[c] = a; vhi[c] = b;
        }
        #pragma unroll
        for (int c4 = 0; c4 < TC; c4 += 4) {
            if (colb + c4 >= fout) continue;
            if (r0 < n)
                *(float4*)(out + (size_t)r0 * fout + colb + c4) =
                    make_float4(vlo[c4], vlo[c4 + 1], vlo[c4 + 2], vlo[c4 + 3]);
            if (r0 + 1 < n)
                *(float4*)(out + (size_t)(r0 + 1) * fout + colb + c4) =
                    make_float4(vhi[c4], vhi[c4 + 1], vhi[c4 + 2], vhi[c4 + 3]);
        }
    }
}

// ======================= CSR build (once per launch) ========================
__global__ void hist_kernel(const int* __restrict__ dst, int* __restrict__ deg)
{
    int e = blockIdx.x * 256 + threadIdx.x;
    if (e < NE) atomicAdd(&deg[dst[e]], 1);
}

// Single-block exclusive scan of deg[NN] -> off/pos; off[NN] = total.
__global__ void __launch_bounds__(1024) scan_kernel(
    const int* __restrict__ deg, int* __restrict__ off, int* __restrict__ pos)
{
    __shared__ int wsum[32];
    __shared__ int carry_s;
    const int tid = threadIdx.x, lane = tid & 31, w = tid >> 5;
    if (tid == 0) carry_s = 0;
    __syncthreads();
    for (int base = 0; base < NN; base += 1024) {
        int idx = base + tid;
        int v = (idx < NN) ? deg[idx] : 0;
        int incl = v;
        #pragma unroll
        for (int d = 1; d < 32; d <<= 1) {
            int t = __shfl_up_sync(~0u, incl, d);
            if (lane >= d) incl += t;
        }
        if (lane == 31) wsum[w] = incl;
        __syncthreads();
        if (w == 0) {
            int s = wsum[lane], si = s;
            #pragma unroll
            for (int d = 1; d < 32; d <<= 1) {
                int t = __shfl_up_sync(~0u, si, d);
                if (lane >= d) si += t;
            }
            wsum[lane] = si - s;                 // exclusive warp offsets
        }
        __syncthreads();
        int excl = incl - v + wsum[w] + carry_s;
        if (idx < NN) { off[idx] = excl; pos[idx] = excl; }
        __syncthreads();
        if (tid == 1023) carry_s = excl + v;
        __syncthreads();
    }
    if (tid == 0) off[NN] = carry_s;
}

__global__ void scatter_kernel(const int* __restrict__ src, const int* __restrict__ dst,
                               int* __restrict__ pos, int* __restrict__ csr)
{
    int e = blockIdx.x * 256 + threadIdx.x;
    if (e < NE) {
        int p = atomicAdd(&pos[dst[e]], 1);
        csr[p] = src[e];
    }
}

// ================== segment-max via CSR: warp per node ======================
// Messages are post-ReLU (>=0): init 0 reproduces where(isfinite(max),.,0).
__device__ __forceinline__ float4 max4(float4 a, float4 b) {
    return make_float4(fmaxf(a.x, b.x), fmaxf(a.y, b.y),
                       fmaxf(a.z, b.z), fmaxf(a.w, b.w));
}

__global__ void __launch_bounds__(256) agg_kernel(
    const int* __restrict__ off, const int* __restrict__ csr,
    const float* __restrict__ m, float* __restrict__ agg)
{
    int node = blockIdx.x * 8 + (threadIdx.x >> 5);
    if (node >= NN) return;
    int lane = threadIdx.x & 31;
    int i = off[node], e1 = off[node + 1];
    float4 mx = make_float4(0.f, 0.f, 0.f, 0.f);
    for (; i + 4 <= e1; i += 4) {
        int s0 = __ldg(&csr[i]),     s1 = __ldg(&csr[i + 1]);
        int s2 = __ldg(&csr[i + 2]), s3 = __ldg(&csr[i + 3]);
        float4 a = *(const float4*)(m + (size_t)s0 * FDIM + lane * 4);
        float4 b = *(const float4*)(m + (size_t)s1 * FDIM + lane * 4);
        float4 c = *(const float4*)(m + (size_t)s2 * FDIM + lane * 4);
        float4 d = *(const float4*)(m + (size_t)s3 * FDIM + lane * 4);
        mx = max4(mx, max4(max4(a, b), max4(c, d)));
    }
    for (; i < e1; i++) {
        int s = __ldg(&csr[i]);
        mx = max4(mx, *(const float4*)(m + (size_t)s * FDIM + lane * 4));
    }
    *(float4*)(agg + (size_t)node * FDIM + lane * 4) = mx;
}

// ============================================================================
extern "C" void kernel_launch(void* const* d_in, const int* in_sizes, int n_in,
                              void* d_out, int out_size)
{
    const float* in_feat  = (const float*)d_in[0];
    const int*   src      = (const int*)  d_in[1];
    const int*   dst      = (const int*)  d_in[2];
    const float* pool_w1  = (const float*)d_in[3];
    const float* pool_b1  = (const float*)d_in[4];
    const float* self_w1  = (const float*)d_in[5];
    const float* self_b1  = (const float*)d_in[6];
    const float* neigh_w1 = (const float*)d_in[7];
    const float* neigh_b1 = (const float*)d_in[8];
    const float* pool_w2  = (const float*)d_in[9];
    const float* pool_b2  = (const float*)d_in[10];
    const float* self_w2  = (const float*)d_in[11];
    const float* self_b2  = (const float*)d_in[12];
    const float* neigh_w2 = (const float*)d_in[13];
    const float* neigh_b2 = (const float*)d_in[14];

    float *m, *agg, *h;
    int *deg, *off, *pos, *csr;
    cudaGetSymbolAddress((void**)&m,   g_m);
    cudaGetSymbolAddress((void**)&agg, g_agg);
    cudaGetSymbolAddress((void**)&h,   g_h);
    cudaGetSymbolAddress((void**)&deg, g_deg);
    cudaGetSymbolAddress((void**)&off, g_off);
    cudaGetSymbolAddress((void**)&pos, g_pos);
    cudaGetSymbolAddress((void**)&csr, g_csr);

    const int ggrid = (NN + 127) / 128;
    const int egrid = (NE + 255) / 256;
    const int ngrid = (NN + 7) / 8;

    // ---- CSR build (shared by both layers) ----
    cudaMemsetAsync(deg, 0, NN * sizeof(int));
    hist_kernel<<<egrid, 256>>>(dst, deg);
    scan_kernel<<<1, 1024>>>(deg, off, pos);
    scatter_kernel<<<egrid, 256>>>(src, dst, pos, csr);

    // ---- layer 1 ----
    gemm_kernel<8><<<ggrid, 256>>>(in_feat, nullptr, pool_w1, nullptr,
                                   pool_b1, nullptr, m, NN, FDIM, 1);
    agg_kernel<<<ngrid, 256>>>(off, csr, m, agg);
    gemm_kernel<8><<<ggrid, 256>>>(in_feat, agg, self_w1, neigh_w1,
                                   self_b1, neigh_b1, h, NN, FDIM, 1);
    // ---- layer 2 ----
    gemm_kernel<8><<<ggrid, 256>>>(h, nullptr, pool_w2, nullptr,
                                   pool_b2, nullptr, m, NN, FDIM, 1);
    agg_kernel<<<ngrid, 256>>>(off, csr, m, agg);
    gemm_kernel<4><<<ggrid, 256>>>(h, agg, self_w2, neigh_w2,
                                   self_b2, neigh_b2, (float*)d_out, NN, NCLS, 0);
}

// round 6
// speedup vs baseline: 3.3836x; 1.7627x over previous
#include <cuda_runtime.h>
#include <cstdint>

#define NN 100000
#define NE 1600000
#define FDIM 128
#define NCLS 40

// ------------------------- device scratch (no allocs) -----------------------
__device__ float g_m[(size_t)NN * FDIM];    // pool output (messages, tf32-rounded)
__device__ float g_agg[(size_t)NN * FDIM];  // segment-max aggregate
__device__ float g_h[(size_t)NN * FDIM];    // layer-1 hidden (tf32-rounded)
__device__ float g_xr[(size_t)NN * FDIM];   // tf32-rounded in_feat
__device__ float g_wr[75776];               // tf32-rounded weights (6 matrices)
__device__ int   g_deg[NN];
__device__ int   g_off[NN + 1];
__device__ int   g_pos[NN];
__device__ int   g_csr[NE];

// weight offsets inside g_wr
#define WR_PW1 0
#define WR_SW1 16384
#define WR_NW1 32768
#define WR_PW2 49152
#define WR_SW2 65536
#define WR_NW2 70656

// ------------------------- PTX helpers --------------------------------------
__device__ __forceinline__ uint32_t smem_to_u32(const void* p) {
    uint32_t a;
    asm("{ .reg .u64 t; cvta.to.shared.u64 t, %1; cvt.u32.u64 %0, t; }"
        : "=r"(a) : "l"(p));
    return a;
}
#define CPASYNC16(sa, ga, sz) \
    asm volatile("cp.async.cg.shared.global [%0], [%1], 16, %2;" \
                 :: "r"(sa), "l"(ga), "r"(sz))
#define CPCOMMIT() asm volatile("cp.async.commit_group;" ::: "memory")
#define CPWAIT(N)  asm volatile("cp.async.wait_group %0;" :: "n"(N) : "memory")

__device__ __forceinline__ float tf32r(float x) {
    uint32_t u;
    asm("cvt.rna.tf32.f32 %0, %1;" : "=r"(u) : "f"(x));
    return __uint_as_float(u);
}

// m16n8k8 tf32 HMMA (row.col, f32 accum). Base PTX (sm_80+): compiles at compute_103.
__device__ __forceinline__ void mma_tf32(float* d, const uint32_t* a, const uint32_t* b)
{
    asm volatile(
        "mma.sync.aligned.m16n8k8.row.col.f32.tf32.tf32.f32 "
        "{%0,%1,%2,%3}, {%4,%5,%6,%7}, {%8,%9}, {%0,%1,%2,%3};"
        : "+f"(d[0]), "+f"(d[1]), "+f"(d[2]), "+f"(d[3])
        : "r"(a[0]), "r"(a[1]), "r"(a[2]), "r"(a[3]),
          "r"(b[0]), "r"(b[1]));
}

// ------------------------- tf32 warp-MMA GEMM --------------------------------
// out[i][j] = act( X0[i,:]·W0[j,:] (+ X1[i,:]·W1[j,:]) + b0[j] (+ b1[j]) )
// BM=128, BN in {128,64}. 256 thr = 8 warps (4 M x 2 N). Warp tile 32 x BN/2.
// Smem tiles [row][k] padded to 36 floats -> conflict-free fragment LDS.
// cp.async double-buffered over 32-k chunks; DUAL accumulates both passes
// into the same register fragments.
template<int BN, bool DUAL, bool ROUND_OUT>
__global__ void __launch_bounds__(256, 2) mma_gemm_kernel(
    const float* __restrict__ X0, const float* __restrict__ X1,
    const float* __restrict__ W0, const float* __restrict__ W1,
    const float* __restrict__ b0, const float* __restrict__ b1,
    float* __restrict__ out, int n, int fout, int do_relu)
{
    constexpr int NF = BN / 16;              // 8-col n-frags per warp
    constexpr int KP = 36;                   // padded k stride (floats)
    extern __shared__ __align__(16) float smem[];
    float* As     = smem;                    // [2][128][KP]
    float* Bs     = smem + 2 * 128 * KP;     // [2][BN][KP]
    float* bias_s = Bs + 2 * BN * KP;        // [BN]

    const int tid   = threadIdx.x;
    const int lane  = tid & 31, wid = tid >> 5;
    const int g     = lane >> 2, tig = lane & 3;
    const int m_base = (wid & 3) * 32;
    const int n_base = (wid >> 2) * (BN / 2);
    const int row0  = blockIdx.x * 128;
    const uint32_t sbA = smem_to_u32(smem);
    const uint32_t sbB = sbA + 2 * 128 * KP * 4;

    if (tid < BN) {
        float bv = 0.f;
        if (tid < fout) { bv = b0[tid]; if (b1 != nullptr) bv += b1[tid]; }
        bias_s[tid] = bv;
    }

    auto load_A = [&](int buf, const float* __restrict__ X, int kc) {
        #pragma unroll
        for (int i = 0; i < 4; i++) {
            int lin = i * 256 + tid;         // 0..1023
            int r = lin >> 3, s = lin & 7;
            int gr = row0 + r;
            int ok = (gr < n);
            const float* src = X + (size_t)(ok ? gr : 0) * 128 + kc + s * 4;
            uint32_t sa = sbA + (uint32_t)(buf * 128 * KP + r * KP) * 4 + s * 16;
            CPASYNC16(sa, src, ok ? 16 : 0);
        }
    };
    auto load_B = [&](int buf, const float* __restrict__ W, int kc) {
        #pragma unroll
        for (int i = 0; i < BN / 32; i++) {
            int lin = i * 256 + tid;         // 0..BN*8-1
            int r = lin >> 3, s = lin & 7;   // r = output col
            int ok = (r < fout);
            const float* src = W + (size_t)(ok ? r : 0) * 128 + kc + s * 4;
            uint32_t sa = sbB + (uint32_t)(buf * BN * KP + r * KP) * 4 + s * 16;
            CPASYNC16(sa, src, ok ? 16 : 0);
        }
    };
    auto load_chunk = [&](int c, int buf) {
        const float* X = (c < 4) ? X0 : X1;
        const float* W = (c < 4) ? W0 : W1;
        int kc = (c & 3) * 32;
        load_A(buf, X, kc);
        load_B(buf, W, kc);
        CPCOMMIT();
    };

    float acc[2][NF][4];
    #pragma unroll
    for (int mt = 0; mt < 2; mt++)
        #pragma unroll
        for (int f = 0; f < NF; f++)
            #pragma unroll
            for (int j = 0; j < 4; j++) acc[mt][f][j] = 0.f;

    const int nch = DUAL ? 8 : 4;
    load_chunk(0, 0);
    load_chunk(1, 1);

    for (int c = 0; c < nch; c++) {
        if (c + 1 < nch) { CPWAIT(1); } else { CPWAIT(0); }
        __syncthreads();
        const int buf = c & 1;
        const float* Ab = As + buf * 128 * KP;
        const float* Bb = Bs + buf * BN * KP;
        #pragma unroll
        for (int kk = 0; kk < 32; kk += 8) {
            uint32_t afr[2][4];
            #pragma unroll
            for (int mt = 0; mt < 2; mt++) {
                int rb = m_base + mt * 16;
                afr[mt][0] = __float_as_uint(Ab[(rb + g) * KP + kk + tig]);
                afr[mt][1] = __float_as_uint(Ab[(rb + 8 + g) * KP + kk + tig]);
                afr[mt][2] = __float_as_uint(Ab[(rb + g) * KP + kk + tig + 4]);
                afr[mt][3] = __float_as_uint(Ab[(rb + 8 + g) * KP + kk + tig + 4]);
            }
            uint32_t bfr[NF][2];
            #pragma unroll
            for (int f = 0; f < NF; f++) {
                int nr = n_base + f * 8 + g;
                bfr[f][0] = __float_as_uint(Bb[nr * KP + kk + tig]);
                bfr[f][1] = __float_as_uint(Bb[nr * KP + kk + tig + 4]);
            }
            #pragma unroll
            for (int mt = 0; mt < 2; mt++)
                #pragma unroll
                for (int f = 0; f < NF; f++)
                    mma_tf32(acc[mt][f], afr[mt], bfr[f]);
        }
        __syncthreads();
        if (c + 2 < nch) load_chunk(c + 2, buf);
    }

    // ---- epilogue: bias + relu (+ tf32 round), direct global store ----
    #pragma unroll
    for (int mt = 0; mt < 2; mt++) {
        int row = row0 + m_base + mt * 16 + g;
        #pragma unroll
        for (int f = 0; f < NF; f++) {
            int col = n_base + f * 8 + 2 * tig;
            if (col >= fout) continue;
            float bx = bias_s[col], by = bias_s[col + 1];
            float v0 = acc[mt][f][0] + bx, v1 = acc[mt][f][1] + by;
            float v2 = acc[mt][f][2] + bx, v3 = acc[mt][f][3] + by;
            if (do_relu) {
                v0 = fmaxf(v0, 0.f); v1 = fmaxf(v1, 0.f);
                v2 = fmaxf(v2, 0.f); v3 = fmaxf(v3, 0.f);
            }
            if (ROUND_OUT) {
                v0 = tf32r(v0); v1 = tf32r(v1);
                v2 = tf32r(v2); v3 = tf32r(v3);
            }
            if (row < n)
                *(float2*)(out + (size_t)row * fout + col) = make_float2(v0, v1);
            if (row + 8 < n)
                *(float2*)(out + (size_t)(row + 8) * fout + col) = make_float2(v2, v3);
        }
    }
}

// ------------------------- prep: tf32 rounding --------------------------------
__global__ void round_x_kernel(const float4* __restrict__ in, float4* __restrict__ out, int n4)
{
    int i = blockIdx.x * 256 + threadIdx.x;
    if (i < n4) {
        float4 v = in[i];
        out[i] = make_float4(tf32r(v.x), tf32r(v.y), tf32r(v.z), tf32r(v.w));
    }
}

__global__ void round_w_kernel(const float* w1, const float* w2, const float* w3,
                               const float* w4, const float* w5, const float* w6,
                               float* __restrict__ wr)
{
    int i = blockIdx.x * 256 + threadIdx.x;   // 0..75775
    const float* s; int off;
    if      (i < 16384) { s = w1; off = i; }
    else if (i < 32768) { s = w2; off = i - 16384; }
    else if (i < 49152) { s = w3; off = i - 32768; }
    else if (i < 65536) { s = w4; off = i - 49152; }
    else if (i < 70656) { s = w5; off = i - 65536; }
    else if (i < 75776) { s = w6; off = i - 70656; }
    else return;
    wr[i] = tf32r(s[off]);
}

// ------------------------- CSR build ------------------------------------------
__global__ void hist_kernel(const int* __restrict__ dst, int* __restrict__ deg)
{
    int e = blockIdx.x * 256 + threadIdx.x;
    if (e < NE) atomicAdd(&deg[dst[e]], 1);
}

__global__ void __launch_bounds__(1024) scan_kernel(
    const int* __restrict__ deg, int* __restrict__ off, int* __restrict__ pos)
{
    __shared__ int wsum[32];
    __shared__ int carry_s;
    const int tid = threadIdx.x, lane = tid & 31, w = tid >> 5;
    if (tid == 0) carry_s = 0;
    __syncthreads();
    for (int base = 0; base < NN; base += 1024) {
        int idx = base + tid;
        int v = (idx < NN) ? deg[idx] : 0;
        int incl = v;
        #pragma unroll
        for (int d = 1; d < 32; d <<= 1) {
            int t = __shfl_up_sync(~0u, incl, d);
            if (lane >= d) incl += t;
        }
        if (lane == 31) wsum[w] = incl;
        __syncthreads();
        if (w == 0) {
            int s = wsum[lane], si = s;
            #pragma unroll
            for (int d = 1; d < 32; d <<= 1) {
                int t = __shfl_up_sync(~0u, si, d);
                if (lane >= d) si += t;
            }
            wsum[lane] = si - s;
        }
        __syncthreads();
        int excl = incl - v + wsum[w] + carry_s;
        if (idx < NN) { off[idx] = excl; pos[idx] = excl; }
        __syncthreads();
        if (tid == 1023) carry_s = excl + v;
        __syncthreads();
    }
    if (tid == 0) off[NN] = carry_s;
}

__global__ void scatter_kernel(const int* __restrict__ src, const int* __restrict__ dst,
                               int* __restrict__ pos, int* __restrict__ csr)
{
    int e = blockIdx.x * 256 + threadIdx.x;
    if (e < NE) {
        int p = atomicAdd(&pos[dst[e]], 1);
        csr[p] = src[e];
    }
}

// ------------------------- segment-max via CSR ---------------------------------
__device__ __forceinline__ float4 max4(float4 a, float4 b) {
    return make_float4(fmaxf(a.x, b.x), fmaxf(a.y, b.y),
                       fmaxf(a.z, b.z), fmaxf(a.w, b.w));
}

__global__ void __launch_bounds__(256) agg_kernel(
    const int* __restrict__ off, const int* __restrict__ csr,
    const float* __restrict__ m, float* __restrict__ agg)
{
    int node = blockIdx.x * 8 + (threadIdx.x >> 5);
    if (node >= NN) return;
    int lane = threadIdx.x & 31;
    int i = off[node], e1 = off[node + 1];
    float4 mx = make_float4(0.f, 0.f, 0.f, 0.f);
    for (; i + 4 <= e1; i += 4) {
        int s0 = __ldg(&csr[i]),     s1 = __ldg(&csr[i + 1]);
        int s2 = __ldg(&csr[i + 2]), s3 = __ldg(&csr[i + 3]);
        float4 a = *(const float4*)(m + (size_t)s0 * FDIM + lane * 4);
        float4 b = *(const float4*)(m + (size_t)s1 * FDIM + lane * 4);
        float4 c = *(const float4*)(m + (size_t)s2 * FDIM + lane * 4);
        float4 d = *(const float4*)(m + (size_t)s3 * FDIM + lane * 4);
        mx = max4(mx, max4(max4(a, b), max4(c, d)));
    }
    for (; i < e1; i++) {
        int s = __ldg(&csr[i]);
        mx = max4(mx, *(const float4*)(m + (size_t)s * FDIM + lane * 4));
    }
    *(float4*)(agg + (size_t)node * FDIM + lane * 4) = mx;
}

// ===============================================================================
extern "C" void kernel_launch(void* const* d_in, const int* in_sizes, int n_in,
                              void* d_out, int out_size)
{
    const float* in_feat  = (const float*)d_in[0];
    const int*   src      = (const int*)  d_in[1];
    const int*   dst      = (const int*)  d_in[2];
    const float* pool_w1  = (const float*)d_in[3];
    const float* pool_b1  = (const float*)d_in[4];
    const float* self_w1  = (const float*)d_in[5];
    const float* self_b1  = (const float*)d_in[6];
    const float* neigh_w1 = (const float*)d_in[7];
    const float* neigh_b1 = (const float*)d_in[8];
    const float* pool_w2  = (const float*)d_in[9];
    const float* pool_b2  = (const float*)d_in[10];
    const float* self_w2  = (const float*)d_in[11];
    const float* self_b2  = (const float*)d_in[12];
    const float* neigh_w2 = (const float*)d_in[13];
    const float* neigh_b2 = (const float*)d_in[14];

    float *m, *agg, *h, *xr, *wr;
    int *deg, *off, *pos, *csr;
    cudaGetSymbolAddress((void**)&m,   g_m);
    cudaGetSymbolAddress((void**)&agg, g_agg);
    cudaGetSymbolAddress((void**)&h,   g_h);
    cudaGetSymbolAddress((void**)&xr,  g_xr);
    cudaGetSymbolAddress((void**)&wr,  g_wr);
    cudaGetSymbolAddress((void**)&deg, g_deg);
    cudaGetSymbolAddress((void**)&off, g_off);
    cudaGetSymbolAddress((void**)&pos, g_pos);
    cudaGetSymbolAddress((void**)&csr, g_csr);

    const int ggrid = (NN + 127) / 128;      // 782
    const int egrid = (NE + 255) / 256;
    const int ngrid = (NN + 7) / 8;
    const int SMEM_128 = (2 * 128 * 36 + 2 * 128 * 36 + 128) * 4;   // 74240 B
    const int SMEM_64  = (2 * 128 * 36 + 2 * 64 * 36 + 64) * 4;     // 55552 B

    cudaFuncSetAttribute(mma_gemm_kernel<128, false, true>,
                         cudaFuncAttributeMaxDynamicSharedMemorySize, SMEM_128);
    cudaFuncSetAttribute(mma_gemm_kernel<128, true, true>,
                         cudaFuncAttributeMaxDynamicSharedMemorySize, SMEM_128);
    cudaFuncSetAttribute(mma_gemm_kernel<64, true, false>,
                         cudaFuncAttributeMaxDynamicSharedMemorySize, SMEM_64);

    // ---- prep: tf32-round inputs & weights; build CSR ----
    const int n4 = NN * FDIM / 4;
    round_x_kernel<<<(n4 + 255) / 256, 256>>>((const float4*)in_feat, (float4*)xr, n4);
    round_w_kernel<<<(75776 + 255) / 256, 256>>>(pool_w1, self_w1, neigh_w1,
                                                 pool_w2, self_w2, neigh_w2, wr);
    cudaMemsetAsync(deg, 0, NN * sizeof(int));
    hist_kernel<<<egrid, 256>>>(dst, deg);
    scan_kernel<<<1, 1024>>>(deg, off, pos);
    scatter_kernel<<<egrid, 256>>>(src, dst, pos, csr);

    // ---- layer 1 ----
    mma_gemm_kernel<128, false, true><<<ggrid, 256, SMEM_128>>>(
        xr, nullptr, wr + WR_PW1, nullptr, pool_b1, nullptr, m, NN, FDIM, 1);
    agg_kernel<<<ngrid, 256>>>(off, csr, m, agg);
    mma_gemm_kernel<128, true, true><<<ggrid, 256, SMEM_128>>>(
        xr, agg, wr + WR_SW1, wr + WR_NW1, self_b1, neigh_b1, h, NN, FDIM, 1);

    // ---- layer 2 ----
    mma_gemm_kernel<128, false, true><<<ggrid, 256, SMEM_128>>>(
        h, nullptr, wr + WR_PW2, nullptr, pool_b2, nullptr, m, NN, FDIM, 1);
    agg_kernel<<<ngrid, 256>>>(off, csr, m, agg);
    mma_gemm_kernel<64, true, false><<<ggrid, 256, SMEM_64>>>(
        h, agg, wr + WR_SW2, wr + WR_NW2, self_b2, neigh_b2, (float*)d_out, NN, NCLS, 0);
}

// round 7
// speedup vs baseline: 4.3482x; 1.2851x over previous
#include <cuda_runtime.h>
#include <cuda_fp16.h>
#include <cstdint>

#define NN 100000
#define NE 1600000
#define FDIM 128
#define NCLS 40

// ------------------------- device scratch (no allocs) -----------------------
__device__ __half g_mh[(size_t)NN * FDIM];  // pool output (messages, fp16)
__device__ float g_agg[(size_t)NN * FDIM];  // segment-max aggregate (fp32)
__device__ float g_h[(size_t)NN * FDIM];    // layer-1 hidden (tf32-rounded)
__device__ float g_xr[(size_t)NN * FDIM];   // tf32-rounded in_feat
__device__ float g_wr[75776];               // tf32-rounded weights (6 matrices)
__device__ int   g_deg[NN];
__device__ int   g_off[NN + 1];
__device__ int   g_pos[NN];
__device__ int   g_csr[NE];
__device__ int   g_part[128];               // scan tile partials

// weight offsets inside g_wr
#define WR_PW1 0
#define WR_SW1 16384
#define WR_NW1 32768
#define WR_PW2 49152
#define WR_SW2 65536
#define WR_NW2 70656

// ------------------------- PTX helpers --------------------------------------
__device__ __forceinline__ uint32_t smem_to_u32(const void* p) {
    uint32_t a;
    asm("{ .reg .u64 t; cvta.to.shared.u64 t, %1; cvt.u32.u64 %0, t; }"
        : "=r"(a) : "l"(p));
    return a;
}
#define CPASYNC16(sa, ga, sz) \
    asm volatile("cp.async.cg.shared.global [%0], [%1], 16, %2;" \
                 :: "r"(sa), "l"(ga), "r"(sz))
#define CPCOMMIT() asm volatile("cp.async.commit_group;" ::: "memory")
#define CPWAIT(N)  asm volatile("cp.async.wait_group %0;" :: "n"(N) : "memory")

__device__ __forceinline__ float tf32r(float x) {
    uint32_t u;
    asm("cvt.rna.tf32.f32 %0, %1;" : "=r"(u) : "f"(x));
    return __uint_as_float(u);
}

// m16n8k8 tf32 HMMA (row.col, f32 accum). Base PTX (sm_80+): compiles at compute_103.
__device__ __forceinline__ void mma_tf32(float* d, const uint32_t* a, const uint32_t* b)
{
    asm volatile(
        "mma.sync.aligned.m16n8k8.row.col.f32.tf32.tf32.f32 "
        "{%0,%1,%2,%3}, {%4,%5,%6,%7}, {%8,%9}, {%0,%1,%2,%3};"
        : "+f"(d[0]), "+f"(d[1]), "+f"(d[2]), "+f"(d[3])
        : "r"(a[0]), "r"(a[1]), "r"(a[2]), "r"(a[3]),
          "r"(b[0]), "r"(b[1]));
}

// ------------------------- tf32 warp-MMA GEMM --------------------------------
// out[i][j] = act( X0[i,:]·W0[j,:] (+ X1[i,:]·W1[j,:]) + b0[j] (+ b1[j]) )
// BM=128, BN in {128,64}. 256 thr = 8 warps (4 M x 2 N). Warp tile 32 x BN/2.
// OUT_HALF: store result as fp16 (exactly representable superset of tf32
// mantissa for in-range values). Else ROUND_OUT rounds fp32 to tf32.
template<int BN, bool DUAL, bool ROUND_OUT, bool OUT_HALF>
__global__ void __launch_bounds__(256, 2) mma_gemm_kernel(
    const float* __restrict__ X0, const float* __restrict__ X1,
    const float* __restrict__ W0, const float* __restrict__ W1,
    const float* __restrict__ b0, const float* __restrict__ b1,
    void* __restrict__ out_v, int n, int fout, int do_relu)
{
    constexpr int NF = BN / 16;              // 8-col n-frags per warp
    constexpr int KP = 36;                   // padded k stride (floats)
    extern __shared__ __align__(16) float smem[];
    float* As     = smem;                    // [2][128][KP]
    float* Bs     = smem + 2 * 128 * KP;     // [2][BN][KP]
    float* bias_s = Bs + 2 * BN * KP;        // [BN]

    const int tid   = threadIdx.x;
    const int lane  = tid & 31, wid = tid >> 5;
    const int g     = lane >> 2, tig = lane & 3;
    const int m_base = (wid & 3) * 32;
    const int n_base = (wid >> 2) * (BN / 2);
    const int row0  = blockIdx.x * 128;
    const uint32_t sbA = smem_to_u32(smem);
    const uint32_t sbB = sbA + 2 * 128 * KP * 4;

    if (tid < BN) {
        float bv = 0.f;
        if (tid < fout) { bv = b0[tid]; if (b1 != nullptr) bv += b1[tid]; }
        bias_s[tid] = bv;
    }

    auto load_A = [&](int buf, const float* __restrict__ X, int kc) {
        #pragma unroll
        for (int i = 0; i < 4; i++) {
            int lin = i * 256 + tid;         // 0..1023
            int r = lin >> 3, s = lin & 7;
            int gr = row0 + r;
            int ok = (gr < n);
            const float* src = X + (size_t)(ok ? gr : 0) * 128 + kc + s * 4;
            uint32_t sa = sbA + (uint32_t)(buf * 128 * KP + r * KP) * 4 + s * 16;
            CPASYNC16(sa, src, ok ? 16 : 0);
        }
    };
    auto load_B = [&](int buf, const float* __restrict__ W, int kc) {
        #pragma unroll
        for (int i = 0; i < BN / 32; i++) {
            int lin = i * 256 + tid;         // 0..BN*8-1
            int r = lin >> 3, s = lin & 7;   // r = output col
            int ok = (r < fout);
            const float* src = W + (size_t)(ok ? r : 0) * 128 + kc + s * 4;
            uint32_t sa = sbB + (uint32_t)(buf * BN * KP + r * KP) * 4 + s * 16;
            CPASYNC16(sa, src, ok ? 16 : 0);
        }
    };
    auto load_chunk = [&](int c, int buf) {
        const float* X = (c < 4) ? X0 : X1;
        const float* W = (c < 4) ? W0 : W1;
        int kc = (c & 3) * 32;
        load_A(buf, X, kc);
        load_B(buf, W, kc);
        CPCOMMIT();
    };

    float acc[2][NF][4];
    #pragma unroll
    for (int mt = 0; mt < 2; mt++)
        #pragma unroll
        for (int f = 0; f < NF; f++)
            #pragma unroll
            for (int j = 0; j < 4; j++) acc[mt][f][j] = 0.f;

    const int nch = DUAL ? 8 : 4;
    load_chunk(0, 0);
    load_chunk(1, 1);

    for (int c = 0; c < nch; c++) {
        if (c + 1 < nch) { CPWAIT(1); } else { CPWAIT(0); }
        __syncthreads();
        const int buf = c & 1;
        const float* Ab = As + buf * 128 * KP;
        const float* Bb = Bs + buf * BN * KP;
        #pragma unroll
        for (int kk = 0; kk < 32; kk += 8) {
            uint32_t afr[2][4];
            #pragma unroll
            for (int mt = 0; mt < 2; mt++) {
                int rb = m_base + mt * 16;
                afr[mt][0] = __float_as_uint(Ab[(rb + g) * KP + kk + tig]);
                afr[mt][1] = __float_as_uint(Ab[(rb + 8 + g) * KP + kk + tig]);
                afr[mt][2] = __float_as_uint(Ab[(rb + g) * KP + kk + tig + 4]);
                afr[mt][3] = __float_as_uint(Ab[(rb + 8 + g) * KP + kk + tig + 4]);
            }
            uint32_t bfr[NF][2];
            #pragma unroll
            for (int f = 0; f < NF; f++) {
                int nr = n_base + f * 8 + g;
                bfr[f][0] = __float_as_uint(Bb[nr * KP + kk + tig]);
                bfr[f][1] = __float_as_uint(Bb[nr * KP + kk + tig + 4]);
            }
            #pragma unroll
            for (int mt = 0; mt < 2; mt++)
                #pragma unroll
                for (int f = 0; f < NF; f++)
                    mma_tf32(acc[mt][f], afr[mt], bfr[f]);
        }
        __syncthreads();
        if (c + 2 < nch) load_chunk(c + 2, buf);
    }

    // ---- epilogue: bias + relu (+ rounding), direct global store ----
    float* outf = (float*)out_v;
    __half* outh = (__half*)out_v;
    #pragma unroll
    for (int mt = 0; mt < 2; mt++) {
        int row = row0 + m_base + mt * 16 + g;
        #pragma unroll
        for (int f = 0; f < NF; f++) {
            int col = n_base + f * 8 + 2 * tig;
            if (col >= fout) continue;
            float bx = bias_s[col], by = bias_s[col + 1];
            float v0 = acc[mt][f][0] + bx, v1 = acc[mt][f][1] + by;
            float v2 = acc[mt][f][2] + bx, v3 = acc[mt][f][3] + by;
            if (do_relu) {
                v0 = fmaxf(v0, 0.f); v1 = fmaxf(v1, 0.f);
                v2 = fmaxf(v2, 0.f); v3 = fmaxf(v3, 0.f);
            }
            if (OUT_HALF) {
                if (row < n)
                    *(__half2*)(outh + (size_t)row * fout + col) =
                        __floats2half2_rn(v0, v1);
                if (row + 8 < n)
                    *(__half2*)(outh + (size_t)(row + 8) * fout + col) =
                        __floats2half2_rn(v2, v3);
            } else {
                if (ROUND_OUT) {
                    v0 = tf32r(v0); v1 = tf32r(v1);
                    v2 = tf32r(v2); v3 = tf32r(v3);
                }
                if (row < n)
                    *(float2*)(outf + (size_t)row * fout + col) = make_float2(v0, v1);
                if (row + 8 < n)
                    *(float2*)(outf + (size_t)(row + 8) * fout + col) = make_float2(v2, v3);
            }
        }
    }
}

// ------------------------- prep: tf32 rounding --------------------------------
__global__ void round_x_kernel(const float4* __restrict__ in, float4* __restrict__ out, int n4)
{
    int i = blockIdx.x * 256 + threadIdx.x;
    if (i < n4) {
        float4 v = in[i];
        out[i] = make_float4(tf32r(v.x), tf32r(v.y), tf32r(v.z), tf32r(v.w));
    }
}

__global__ void round_w_kernel(const float* w1, const float* w2, const float* w3,
                               const float* w4, const float* w5, const float* w6,
                               float* __restrict__ wr)
{
    int i = blockIdx.x * 256 + threadIdx.x;   // 0..75775
    const float* s; int off;
    if      (i < 16384) { s = w1; off = i; }
    else if (i < 32768) { s = w2; off = i - 16384; }
    else if (i < 49152) { s = w3; off = i - 32768; }
    else if (i < 65536) { s = w4; off = i - 49152; }
    else if (i < 70656) { s = w5; off = i - 65536; }
    else if (i < 75776) { s = w6; off = i - 70656; }
    else return;
    wr[i] = tf32r(s[off]);
}

// ------------------------- CSR build ------------------------------------------
__global__ void hist_kernel(const int* __restrict__ dst, int* __restrict__ deg)
{
    int e = blockIdx.x * 256 + threadIdx.x;
    if (e < NE) atomicAdd(&deg[dst[e]], 1);
}

// Phase A: per-1024-tile exclusive scan; tile sums to part[]. grid = 98 x 1024.
__global__ void __launch_bounds__(1024) scanA_kernel(
    const int* __restrict__ deg, int* __restrict__ off, int* __restrict__ part)
{
    __shared__ int wsum[32];
    const int tid = threadIdx.x, lane = tid & 31, w = tid >> 5;
    int idx = blockIdx.x * 1024 + tid;
    int v = (idx < NN) ? deg[idx] : 0;
    int incl = v;
    #pragma unroll
    for (int d = 1; d < 32; d <<= 1) {
        int t = __shfl_up_sync(~0u, incl, d);
        if (lane >= d) incl += t;
    }
    if (lane == 31) wsum[w] = incl;
    __syncthreads();
    if (w == 0) {
        int s = wsum[lane], si = s;
        #pragma unroll
        for (int d = 1; d < 32; d <<= 1) {
            int t = __shfl_up_sync(~0u, si, d);
            if (lane >= d) si += t;
        }
        wsum[lane] = si - s;
    }
    __syncthreads();
    int excl = incl - v + wsum[w];
    if (idx < NN) off[idx] = excl;
    if (tid == 1023) part[blockIdx.x] = excl + v;
}

// Phase B: scan the 98 tile sums (1 block, 128 threads). Writes off[NN] = total.
__global__ void __launch_bounds__(128) scanB_kernel(int* __restrict__ part,
                                                    int* __restrict__ off, int ntiles)
{
    __shared__ int wsum[4];
    const int tid = threadIdx.x, lane = tid & 31, w = tid >> 5;
    int v = (tid < ntiles) ? part[tid] : 0;
    int incl = v;
    #pragma unroll
    for (int d = 1; d < 32; d <<= 1) {
        int t = __shfl_up_sync(~0u, incl, d);
        if (lane >= d) incl += t;
    }
    if (lane == 31) wsum[w] = incl;
    __syncthreads();
    int woff = 0;
    #pragma unroll
    for (int i = 0; i < 4; i++) if (i < w) woff += wsum[i];
    int excl = incl - v + woff;
    if (tid < ntiles) part[tid] = excl;
    if (tid == 127) off[NN] = excl + v;
}

// Phase C: add tile prefix; fill pos.
__global__ void scanC_kernel(int* __restrict__ off, int* __restrict__ pos,
                             const int* __restrict__ part)
{
    int idx = blockIdx.x * 256 + threadIdx.x;
    if (idx < NN) {
        int o = off[idx] + part[idx >> 10];
        off[idx] = o;
        pos[idx] = o;
    }
}

__global__ void scatter_kernel(const int* __restrict__ src, const int* __restrict__ dst,
                               int* __restrict__ pos, int* __restrict__ csr)
{
    int e = blockIdx.x * 256 + threadIdx.x;
    if (e < NE) {
        int p = atomicAdd(&pos[dst[e]], 1);
        csr[p] = src[e];
    }
}

// ------------------------- segment-max via CSR (fp16 gather) -------------------
// m is fp16 (same 10-bit mantissa as tf32 -> no extra error vs tf32 pipeline);
// values post-ReLU >= 0, init 0 reproduces where(isfinite(max),.,0).
__global__ void __launch_bounds__(256) agg_kernel(
    const int* __restrict__ off, const int* __restrict__ csr,
    const __half2* __restrict__ m2, float* __restrict__ agg)
{
    int node = blockIdx.x * 8 + (threadIdx.x >> 5);
    if (node >= NN) return;
    int lane = threadIdx.x & 31;
    int i = off[node], e1 = off[node + 1];
    const int co = lane * 2;                 // half2 column offset (2 per lane)
    __half2 mx0 = __float2half2_rn(0.f), mx1 = mx0;
    for (; i + 4 <= e1; i += 4) {
        int s0 = __ldg(&csr[i]),     s1 = __ldg(&csr[i + 1]);
        int s2 = __ldg(&csr[i + 2]), s3 = __ldg(&csr[i + 3]);
        const __half2* p0 = m2 + (size_t)s0 * 64 + co;
        const __half2* p1 = m2 + (size_t)s1 * 64 + co;
        const __half2* p2 = m2 + (size_t)s2 * 64 + co;
        const __half2* p3 = m2 + (size_t)s3 * 64 + co;
        __half2 a0 = p0[0], a1 = p0[1];
        __half2 b0 = p1[0], b1 = p1[1];
        __half2 c0 = p2[0], c1 = p2[1];
        __half2 d0 = p3[0], d1 = p3[1];
        mx0 = __hmax2(mx0, __hmax2(__hmax2(a0, b0), __hmax2(c0, d0)));
        mx1 = __hmax2(mx1, __hmax2(__hmax2(a1, b1), __hmax2(c1, d1)));
    }
    for (; i < e1; i++) {
        int s = __ldg(&csr[i]);
        const __half2* p = m2 + (size_t)s * 64 + co;
        mx0 = __hmax2(mx0, p[0]);
        mx1 = __hmax2(mx1, p[1]);
    }
    float2 f0 = __half22float2(mx0), f1 = __half22float2(mx1);
    *(float4*)(agg + (size_t)node * FDIM + lane * 4) =
        make_float4(f0.x, f0.y, f1.x, f1.y);
}

// ===============================================================================
extern "C" void kernel_launch(void* const* d_in, const int* in_sizes, int n_in,
                              void* d_out, int out_size)
{
    const float* in_feat  = (const float*)d_in[0];
    const int*   src      = (const int*)  d_in[1];
    const int*   dst      = (const int*)  d_in[2];
    const float* pool_w1  = (const float*)d_in[3];
    const float* pool_b1  = (const float*)d_in[4];
    const float* self_w1  = (const float*)d_in[5];
    const float* self_b1  = (const float*)d_in[6];
    const float* neigh_w1 = (const float*)d_in[7];
    const float* neigh_b1 = (const float*)d_in[8];
    const float* pool_w2  = (const float*)d_in[9];
    const float* pool_b2  = (const float*)d_in[10];
    const float* self_w2  = (const float*)d_in[11];
    const float* self_b2  = (const float*)d_in[12];
    const float* neigh_w2 = (const float*)d_in[13];
    const float* neigh_b2 = (const float*)d_in[14];

    __half* mh;
    float *agg, *h, *xr, *wr;
    int *deg, *off, *pos, *csr, *part;
    cudaGetSymbolAddress((void**)&mh,   g_mh);
    cudaGetSymbolAddress((void**)&agg,  g_agg);
    cudaGetSymbolAddress((void**)&h,    g_h);
    cudaGetSymbolAddress((void**)&xr,   g_xr);
    cudaGetSymbolAddress((void**)&wr,   g_wr);
    cudaGetSymbolAddress((void**)&deg,  g_deg);
    cudaGetSymbolAddress((void**)&off,  g_off);
    cudaGetSymbolAddress((void**)&pos,  g_pos);
    cudaGetSymbolAddress((void**)&csr,  g_csr);
    cudaGetSymbolAddress((void**)&part, g_part);

    const int ggrid  = (NN + 127) / 128;     // 782
    const int egrid  = (NE + 255) / 256;
    const int ngrid  = (NN + 7) / 8;
    const int ntiles = (NN + 1023) / 1024;   // 98
    const int SMEM_128 = (2 * 128 * 36 + 2 * 128 * 36 + 128) * 4;   // 74240 B
    const int SMEM_64  = (2 * 128 * 36 + 2 * 64 * 36 + 64) * 4;     // 55552 B

    cudaFuncSetAttribute(mma_gemm_kernel<128, false, false, true>,
                         cudaFuncAttributeMaxDynamicSharedMemorySize, SMEM_128);
    cudaFuncSetAttribute(mma_gemm_kernel<128, true, true, false>,
                         cudaFuncAttributeMaxDynamicSharedMemorySize, SMEM_128);
    cudaFuncSetAttribute(mma_gemm_kernel<64, true, false, false>,
                         cudaFuncAttributeMaxDynamicSharedMemorySize, SMEM_64);

    // ---- prep: tf32-round inputs & weights; build CSR ----
    const int n4 = NN * FDIM / 4;
    round_x_kernel<<<(n4 + 255) / 256, 256>>>((const float4*)in_feat, (float4*)xr, n4);
    round_w_kernel<<<(75776 + 255) / 256, 256>>>(pool_w1, self_w1, neigh_w1,
                                                 pool_w2, self_w2, neigh_w2, wr);
    cudaMemsetAsync(deg, 0, NN * sizeof(int));
    hist_kernel<<<egrid, 256>>>(dst, deg);
    scanA_kernel<<<ntiles, 1024>>>(deg, off, part);
    scanB_kernel<<<1, 128>>>(part, off, ntiles);
    scanC_kernel<<<(NN + 255) / 256, 256>>>(off, pos, part);
    scatter_kernel<<<egrid, 256>>>(src, dst, pos, csr);

    // ---- layer 1 ----
    mma_gemm_kernel<128, false, false, true><<<ggrid, 256, SMEM_128>>>(
        xr, nullptr, wr + WR_PW1, nullptr, pool_b1, nullptr, mh, NN, FDIM, 1);
    agg_kernel<<<ngrid, 256>>>(off, csr, (const __half2*)mh, agg);
    mma_gemm_kernel<128, true, true, false><<<ggrid, 256, SMEM_128>>>(
        xr, agg, wr + WR_SW1, wr + WR_NW1, self_b1, neigh_b1, h, NN, FDIM, 1);

    // ---- layer 2 ----
    mma_gemm_kernel<128, false, false, true><<<ggrid, 256, SMEM_128>>>(
        h, nullptr, wr + WR_PW2, nullptr, pool_b2, nullptr, mh, NN, FDIM, 1);
    agg_kernel<<<ngrid, 256>>>(off, csr, (const __half2*)mh, agg);
    mma_gemm_kernel<64, true, false, false><<<ggrid, 256, SMEM_64>>>(
        h, agg, wr + WR_SW2, wr + WR_NW2, self_b2, neigh_b2, (float*)d_out, NN, NCLS, 0);
}

// round 8
// speedup vs baseline: 5.6696x; 1.3039x over previous
#include <cuda_runtime.h>
#include <cuda_fp16.h>
#include <cstdint>

#define NN 100000
#define NE 1600000
#define FDIM 128
#define NCLS 40

// ------------------------- device scratch (no allocs) -----------------------
__device__ __align__(16) __half g_mh[(size_t)NN * FDIM];   // pool messages (fp16)
__device__ __align__(16) __half g_aggh[(size_t)NN * FDIM]; // segment-max agg (fp16)
__device__ __align__(16) __half g_hh[(size_t)NN * FDIM];   // layer-1 hidden (fp16)
__device__ __align__(16) __half g_xh[(size_t)NN * FDIM];   // fp16 in_feat
__device__ __align__(16) __half g_wh[75776];               // fp16 weights (6 matrices)
__device__ int   g_deg[NN];
__device__ int   g_off[NN + 1];
__device__ int   g_pos[NN];
__device__ int   g_csr[NE];
__device__ int   g_part[128];               // scan tile partials

// weight offsets inside g_wh
#define WR_PW1 0
#define WR_SW1 16384
#define WR_NW1 32768
#define WR_PW2 49152
#define WR_SW2 65536
#define WR_NW2 70656

// ------------------------- PTX helpers --------------------------------------
__device__ __forceinline__ uint32_t smem_to_u32(const void* p) {
    uint32_t a;
    asm("{ .reg .u64 t; cvta.to.shared.u64 t, %1; cvt.u32.u64 %0, t; }"
        : "=r"(a) : "l"(p));
    return a;
}
#define CPASYNC16(sa, ga, sz) \
    asm volatile("cp.async.cg.shared.global [%0], [%1], 16, %2;" \
                 :: "r"(sa), "l"(ga), "r"(sz))
#define CPCOMMIT() asm volatile("cp.async.commit_group;" ::: "memory")
#define CPWAIT(N)  asm volatile("cp.async.wait_group %0;" :: "n"(N) : "memory")

// m16n8k16 fp16 HMMA, f32 accum. Base PTX (sm_80+): compiles at compute_103.
__device__ __forceinline__ void mma_f16(float* d, const uint32_t* a, const uint32_t* b)
{
    asm volatile(
        "mma.sync.aligned.m16n8k16.row.col.f32.f16.f16.f32 "
        "{%0,%1,%2,%3}, {%4,%5,%6,%7}, {%8,%9}, {%0,%1,%2,%3};"
        : "+f"(d[0]), "+f"(d[1]), "+f"(d[2]), "+f"(d[3])
        : "r"(a[0]), "r"(a[1]), "r"(a[2]), "r"(a[3]),
          "r"(b[0]), "r"(b[1]));
}

// ------------------------- fp16 warp-MMA GEMM --------------------------------
// out[i][j] = act( X0[i,:]·W0[j,:] (+ X1[i,:]·W1[j,:]) + b0[j] (+ b1[j]) )
// X fp16 [n,128], W fp16 [fout,128]. BM=128, BN in {128,64}. 256 thr = 8 warps
// (4 M x 2 N), warp tile 32 x BN/2. K chunked at 64, double-buffered cp.async.
// Smem rows padded to 72 halves -> all fragment LDS.32 conflict-free.
template<int BN, bool DUAL, bool OUT_HALF>
__global__ void __launch_bounds__(256, 2) mma_gemm_kernel(
    const __half* __restrict__ X0, const __half* __restrict__ X1,
    const __half* __restrict__ W0, const __half* __restrict__ W1,
    const float* __restrict__ b0, const float* __restrict__ b1,
    void* __restrict__ out_v, int n, int fout, int do_relu)
{
    constexpr int NF = BN / 16;              // 8-col n-frags per warp
    constexpr int KP = 72;                   // padded k stride (halves)
    extern __shared__ __align__(16) __half smem_h[];
    __half* As = smem_h;                     // [2][128*KP]
    __half* Bs = smem_h + 2 * 128 * KP;      // [2][BN*KP]
    float* bias_s = (float*)(smem_h + 2 * 128 * KP + 2 * BN * KP);

    const int tid   = threadIdx.x;
    const int lane  = tid & 31, wid = tid >> 5;
    const int g     = lane >> 2, tig = lane & 3;
    const int m_base = (wid & 3) * 32;
    const int n_base = (wid >> 2) * (BN / 2);
    const int row0  = blockIdx.x * 128;
    const uint32_t sbA = smem_to_u32(smem_h);
    const uint32_t sbB = sbA + 2 * 128 * KP * 2;

    if (tid < BN) {
        float bv = 0.f;
        if (tid < fout) { bv = b0[tid]; if (b1 != nullptr) bv += b1[tid]; }
        bias_s[tid] = bv;
    }

    // chunk c: pass = c>>1 (X0/W0 then X1/W1), kc = (c&1)*64
    auto load_chunk = [&](int c, int buf) {
        const __half* X = (c < 2) ? X0 : X1;
        const __half* W = (c < 2) ? W0 : W1;
        const int kc = (c & 1) * 64;
        #pragma unroll
        for (int i = 0; i < 4; i++) {        // A: 128 rows x 8 segs
            int lin = i * 256 + tid;
            int r = lin >> 3, s = lin & 7;
            int gr = row0 + r;
            int ok = (gr < n);
            const __half* src = X + (size_t)(ok ? gr : 0) * 128 + kc + s * 8;
            uint32_t sa = sbA + (uint32_t)(buf * 128 * KP + r * KP + s * 8) * 2;
            CPASYNC16(sa, src, ok ? 16 : 0);
        }
        #pragma unroll
        for (int i = 0; i < BN / 32; i++) {  // B: BN rows x 8 segs
            int lin = i * 256 + tid;
            int r = lin >> 3, s = lin & 7;
            int ok = (r < fout);
            const __half* src = W + (size_t)(ok ? r : 0) * 128 + kc + s * 8;
            uint32_t sa = sbB + (uint32_t)(buf * BN * KP + r * KP + s * 8) * 2;
            CPASYNC16(sa, src, ok ? 16 : 0);
        }
        CPCOMMIT();
    };

    float acc[2][NF][4];
    #pragma unroll
    for (int mt = 0; mt < 2; mt++)
        #pragma unroll
        for (int f = 0; f < NF; f++)
            #pragma unroll
            for (int j = 0; j < 4; j++) acc[mt][f][j] = 0.f;

    const int nch = DUAL ? 4 : 2;
    load_chunk(0, 0);
    load_chunk(1, 1);

    for (int c = 0; c < nch; c++) {
        if (c + 1 < nch) { CPWAIT(1); } else { CPWAIT(0); }
        __syncthreads();
        const int buf = c & 1;
        const __half* Ab = As + buf * 128 * KP;
        const __half* Bb = Bs + buf * BN * KP;
        #pragma unroll
        for (int kk = 0; kk < 64; kk += 16) {
            uint32_t afr[2][4];
            #pragma unroll
            for (int mt = 0; mt < 2; mt++) {
                int rb = m_base + mt * 16 + g;
                afr[mt][0] = *(const uint32_t*)&Ab[(rb)     * KP + kk + 2 * tig];
                afr[mt][1] = *(const uint32_t*)&Ab[(rb + 8) * KP + kk + 2 * tig];
                afr[mt][2] = *(const uint32_t*)&Ab[(rb)     * KP + kk + 8 + 2 * tig];
                afr[mt][3] = *(const uint32_t*)&Ab[(rb + 8) * KP + kk + 8 + 2 * tig];
            }
            uint32_t bfr[NF][2];
            #pragma unroll
            for (int f = 0; f < NF; f++) {
                int nr = n_base + f * 8 + g;
                bfr[f][0] = *(const uint32_t*)&Bb[nr * KP + kk + 2 * tig];
                bfr[f][1] = *(const uint32_t*)&Bb[nr * KP + kk + 8 + 2 * tig];
            }
            #pragma unroll
            for (int mt = 0; mt < 2; mt++)
                #pragma unroll
                for (int f = 0; f < NF; f++)
                    mma_f16(acc[mt][f], afr[mt], bfr[f]);
        }
        __syncthreads();
        if (c + 2 < nch) load_chunk(c + 2, buf);
    }

    // ---- epilogue: bias + relu, direct global store ----
    float* outf = (float*)out_v;
    __half* outh = (__half*)out_v;
    #pragma unroll
    for (int mt = 0; mt < 2; mt++) {
        int row = row0 + m_base + mt * 16 + g;
        #pragma unroll
        for (int f = 0; f < NF; f++) {
            int col = n_base + f * 8 + 2 * tig;
            if (col >= fout) continue;
            float bx = bias_s[col], by = bias_s[col + 1];
            float v0 = acc[mt][f][0] + bx, v1 = acc[mt][f][1] + by;
            float v2 = acc[mt][f][2] + bx, v3 = acc[mt][f][3] + by;
            if (do_relu) {
                v0 = fmaxf(v0, 0.f); v1 = fmaxf(v1, 0.f);
                v2 = fmaxf(v2, 0.f); v3 = fmaxf(v3, 0.f);
            }
            if (OUT_HALF) {
                if (row < n)
                    *(__half2*)(outh + (size_t)row * fout + col) =
                        __floats2half2_rn(v0, v1);
                if (row + 8 < n)
                    *(__half2*)(outh + (size_t)(row + 8) * fout + col) =
                        __floats2half2_rn(v2, v3);
            } else {
                if (row < n)
                    *(float2*)(outf + (size_t)row * fout + col) = make_float2(v0, v1);
                if (row + 8 < n)
                    *(float2*)(outf + (size_t)(row + 8) * fout + col) = make_float2(v2, v3);
            }
        }
    }
}

// ------------------------- prep: fp16 conversion ------------------------------
__global__ void conv_x_kernel(const float4* __restrict__ in, __half2* __restrict__ out, int n4)
{
    int i = blockIdx.x * 256 + threadIdx.x;
    if (i < n4) {
        float4 v = in[i];
        out[i * 2 + 0] = __floats2half2_rn(v.x, v.y);
        out[i * 2 + 1] = __floats2half2_rn(v.z, v.w);
    }
}

__global__ void conv_w_kernel(const float* w1, const float* w2, const float* w3,
                              const float* w4, const float* w5, const float* w6,
                              __half* __restrict__ wh)
{
    int i = blockIdx.x * 256 + threadIdx.x;   // 0..75775
    const float* s; int off;
    if      (i < 16384) { s = w1; off = i; }
    else if (i < 32768) { s = w2; off = i - 16384; }
    else if (i < 49152) { s = w3; off = i - 32768; }
    else if (i < 65536) { s = w4; off = i - 49152; }
    else if (i < 70656) { s = w5; off = i - 65536; }
    else if (i < 75776) { s = w6; off = i - 70656; }
    else return;
    wh[i] = __float2half_rn(s[off]);
}

// ------------------------- CSR build ------------------------------------------
__global__ void hist_kernel(const int* __restrict__ dst, int* __restrict__ deg)
{
    int e = blockIdx.x * 256 + threadIdx.x;
    if (e < NE) atomicAdd(&deg[dst[e]], 1);
}

// Phase A: per-1024-tile exclusive scan; tile sums to part[].
__global__ void __launch_bounds__(1024) scanA_kernel(
    const int* __restrict__ deg, int* __restrict__ off, int* __restrict__ part)
{
    __shared__ int wsum[32];
    const int tid = threadIdx.x, lane = tid & 31, w = tid >> 5;
    int idx = blockIdx.x * 1024 + tid;
    int v = (idx < NN) ? deg[idx] : 0;
    int incl = v;
    #pragma unroll
    for (int d = 1; d < 32; d <<= 1) {
        int t = __shfl_up_sync(~0u, incl, d);
        if (lane >= d) incl += t;
    }
    if (lane == 31) wsum[w] = incl;
    __syncthreads();
    if (w == 0) {
        int s = wsum[lane], si = s;
        #pragma unroll
        for (int d = 1; d < 32; d <<= 1) {
            int t = __shfl_up_sync(~0u, si, d);
            if (lane >= d) si += t;
        }
        wsum[lane] = si - s;
    }
    __syncthreads();
    int excl = incl - v + wsum[w];
    if (idx < NN) off[idx] = excl;
    if (tid == 1023) part[blockIdx.x] = excl + v;
}

// Phase B: scan the tile sums (1 block). Writes off[NN] = total.
__global__ void __launch_bounds__(128) scanB_kernel(int* __restrict__ part,
                                                    int* __restrict__ off, int ntiles)
{
    __shared__ int wsum[4];
    const int tid = threadIdx.x, lane = tid & 31, w = tid >> 5;
    int v = (tid < ntiles) ? part[tid] : 0;
    int incl = v;
    #pragma unroll
    for (int d = 1; d < 32; d <<= 1) {
        int t = __shfl_up_sync(~0u, incl, d);
        if (lane >= d) incl += t;
    }
    if (lane == 31) wsum[w] = incl;
    __syncthreads();
    int woff = 0;
    #pragma unroll
    for (int i = 0; i < 4; i++) if (i < w) woff += wsum[i];
    int excl = incl - v + woff;
    if (tid < ntiles) part[tid] = excl;
    if (tid == 127) off[NN] = excl + v;
}

// Phase C: add tile prefix; fill pos.
__global__ void scanC_kernel(int* __restrict__ off, int* __restrict__ pos,
                             const int* __restrict__ part)
{
    int idx = blockIdx.x * 256 + threadIdx.x;
    if (idx < NN) {
        int o = off[idx] + part[idx >> 10];
        off[idx] = o;
        pos[idx] = o;
    }
}

__global__ void scatter_kernel(const int* __restrict__ src, const int* __restrict__ dst,
                               int* __restrict__ pos, int* __restrict__ csr)
{
    int e = blockIdx.x * 256 + threadIdx.x;
    if (e < NE) {
        int p = atomicAdd(&pos[dst[e]], 1);
        csr[p] = src[e];
    }
}

// ------------------------- segment-max via CSR (fp16 in & out) -----------------
// Post-ReLU values >= 0: init 0 reproduces where(isfinite(max),.,0).
__global__ void __launch_bounds__(256) agg_kernel(
    const int* __restrict__ off, const int* __restrict__ csr,
    const __half2* __restrict__ m2, __half2* __restrict__ agg2)
{
    int node = blockIdx.x * 8 + (threadIdx.x >> 5);
    if (node >= NN) return;
    int lane = threadIdx.x & 31;
    int i = off[node], e1 = off[node + 1];
    const int co = lane * 2;                 // half2 offset (2 per lane)
    __half2 mx0 = __float2half2_rn(0.f), mx1 = mx0;
    for (; i + 4 <= e1; i += 4) {
        int s0 = __ldg(&csr[i]),     s1 = __ldg(&csr[i + 1]);
        int s2 = __ldg(&csr[i + 2]), s3 = __ldg(&csr[i + 3]);
        const __half2* p0 = m2 + (size_t)s0 * 64 + co;
        const __half2* p1 = m2 + (size_t)s1 * 64 + co;
        const __half2* p2 = m2 + (size_t)s2 * 64 + co;
        const __half2* p3 = m2 + (size_t)s3 * 64 + co;
        __half2 a0 = p0[0], a1 = p0[1];
        __half2 b0 = p1[0], b1 = p1[1];
        __half2 c0 = p2[0], c1 = p2[1];
        __half2 d0 = p3[0], d1 = p3[1];
        mx0 = __hmax2(mx0, __hmax2(__hmax2(a0, b0), __hmax2(c0, d0)));
        mx1 = __hmax2(mx1, __hmax2(__hmax2(a1, b1), __hmax2(c1, d1)));
    }
    for (; i < e1; i++) {
        int s = __ldg(&csr[i]);
        const __half2* p = m2 + (size_t)s * 64 + co;
        mx0 = __hmax2(mx0, p[0]);
        mx1 = __hmax2(mx1, p[1]);
    }
    agg2[(size_t)node * 64 + co]     = mx0;
    agg2[(size_t)node * 64 + co + 1] = mx1;
}

// ===============================================================================
extern "C" void kernel_launch(void* const* d_in, const int* in_sizes, int n_in,
                              void* d_out, int out_size)
{
    const float* in_feat  = (const float*)d_in[0];
    const int*   src      = (const int*)  d_in[1];
    const int*   dst      = (const int*)  d_in[2];
    const float* pool_w1  = (const float*)d_in[3];
    const float* pool_b1  = (const float*)d_in[4];
    const float* self_w1  = (const float*)d_in[5];
    const float* self_b1  = (const float*)d_in[6];
    const float* neigh_w1 = (const float*)d_in[7];
    const float* neigh_b1 = (const float*)d_in[8];
    const float* pool_w2  = (const float*)d_in[9];
    const float* pool_b2  = (const float*)d_in[10];
    const float* self_w2  = (const float*)d_in[11];
    const float* self_b2  = (const float*)d_in[12];
    const float* neigh_w2 = (const float*)d_in[13];
    const float* neigh_b2 = (const float*)d_in[14];

    __half *mh, *aggh, *hh, *xh, *wh;
    int *deg, *off, *pos, *csr, *part;
    cudaGetSymbolAddress((void**)&mh,   g_mh);
    cudaGetSymbolAddress((void**)&aggh, g_aggh);
    cudaGetSymbolAddress((void**)&hh,   g_hh);
    cudaGetSymbolAddress((void**)&xh,   g_xh);
    cudaGetSymbolAddress((void**)&wh,   g_wh);
    cudaGetSymbolAddress((void**)&deg,  g_deg);
    cudaGetSymbolAddress((void**)&off,  g_off);
    cudaGetSymbolAddress((void**)&pos,  g_pos);
    cudaGetSymbolAddress((void**)&csr,  g_csr);
    cudaGetSymbolAddress((void**)&part, g_part);

    const int ggrid  = (NN + 127) / 128;     // 782
    const int egrid  = (NE + 255) / 256;
    const int ngrid  = (NN + 7) / 8;
    const int ntiles = (NN + 1023) / 1024;   // 98
    const int SMEM_128 = (2 * 128 * 72 + 2 * 128 * 72) * 2 + 128 * 4;  // 74240 B
    const int SMEM_64  = (2 * 128 * 72 + 2 * 64 * 72) * 2 + 64 * 4;    // 55552 B

    cudaFuncSetAttribute(mma_gemm_kernel<128, false, true>,
                         cudaFuncAttributeMaxDynamicSharedMemorySize, SMEM_128);
    cudaFuncSetAttribute(mma_gemm_kernel<128, true, true>,
                         cudaFuncAttributeMaxDynamicSharedMemorySize, SMEM_128);
    cudaFuncSetAttribute(mma_gemm_kernel<64, true, false>,
                         cudaFuncAttributeMaxDynamicSharedMemorySize, SMEM_64);

    // ---- prep: fp16 conversion; build CSR ----
    const int n4 = NN * FDIM / 4;
    conv_x_kernel<<<(n4 + 255) / 256, 256>>>((const float4*)in_feat, (__half2*)xh, n4);
    conv_w_kernel<<<(75776 + 255) / 256, 256>>>(pool_w1, self_w1, neigh_w1,
                                                pool_w2, self_w2, neigh_w2, wh);
    cudaMemsetAsync(deg, 0, NN * sizeof(int));
    hist_kernel<<<egrid, 256>>>(dst, deg);
    scanA_kernel<<<ntiles, 1024>>>(deg, off, part);
    scanB_kernel<<<1, 128>>>(part, off, ntiles);
    scanC_kernel<<<(NN + 255) / 256, 256>>>(off, pos, part);
    scatter_kernel<<<egrid, 256>>>(src, dst, pos, csr);

    // ---- layer 1 ----
    mma_gemm_kernel<128, false, true><<<ggrid, 256, SMEM_128>>>(
        xh, nullptr, wh + WR_PW1, nullptr, pool_b1, nullptr, mh, NN, FDIM, 1);
    agg_kernel<<<ngrid, 256>>>(off, csr, (const __half2*)mh, (__half2*)aggh);
    mma_gemm_kernel<128, true, true><<<ggrid, 256, SMEM_128>>>(
        xh, aggh, wh + WR_SW1, wh + WR_NW1, self_b1, neigh_b1, hh, NN, FDIM, 1);

    // ---- layer 2 ----
    mma_gemm_kernel<128, false, true><<<ggrid, 256, SMEM_128>>>(
        hh, nullptr, wh + WR_PW2, nullptr, pool_b2, nullptr, mh, NN, FDIM, 1);
    agg_kernel<<<ngrid, 256>>>(off, csr, (const __half2*)mh, (__half2*)aggh);
    mma_gemm_kernel<64, true, false><<<ggrid, 256, SMEM_64>>>(
        hh, aggh, wh + WR_SW2, wh + WR_NW2, self_b2, neigh_b2, (float*)d_out, NN, NCLS, 0);
}

// round 9
// speedup vs baseline: 5.8863x; 1.0382x over previous
#include <cuda_runtime.h>
#include <cuda_fp16.h>
#include <cstdint>

#define NN 100000
#define NE 1600000
#define FDIM 128
#define NCLS 40

// ------------------------- device scratch (no allocs) -----------------------
__device__ __align__(16) __half g_mh[(size_t)NN * FDIM];   // pool messages (fp16)
__device__ __align__(16) __half g_aggh[(size_t)NN * FDIM]; // segment-max agg (fp16)
__device__ __align__(16) __half g_hh[(size_t)NN * FDIM];   // layer-1 hidden (fp16)
__device__ __align__(16) __half g_xh[(size_t)NN * FDIM];   // fp16 in_feat
__device__ __align__(16) __half g_wh[75776];               // fp16 weights (6 matrices)
__device__ int   g_deg[NN];
__device__ int   g_off[NN + 1];
__device__ int   g_pos[NN];
__device__ int   g_csr[NE];
__device__ int   g_part[128];               // scan tile partials

// weight offsets inside g_wh
#define WR_PW1 0
#define WR_SW1 16384
#define WR_NW1 32768
#define WR_PW2 49152
#define WR_SW2 65536
#define WR_NW2 70656

// ------------------------- PTX helpers --------------------------------------
__device__ __forceinline__ uint32_t smem_to_u32(const void* p) {
    uint32_t a;
    asm("{ .reg .u64 t; cvta.to.shared.u64 t, %1; cvt.u32.u64 %0, t; }"
        : "=r"(a) : "l"(p));
    return a;
}
#define CPASYNC16(sa, ga, sz) \
    asm volatile("cp.async.cg.shared.global [%0], [%1], 16, %2;" \
                 :: "r"(sa), "l"(ga), "r"(sz))
#define CPCOMMIT() asm volatile("cp.async.commit_group;" ::: "memory")
#define CPWAIT(N)  asm volatile("cp.async.wait_group %0;" :: "n"(N) : "memory")

// m16n8k16 fp16 HMMA, f32 accum. Base PTX (sm_80+): compiles at compute_103.
__device__ __forceinline__ void mma_f16(float* d, const uint32_t* a, const uint32_t* b)
{
    asm volatile(
        "mma.sync.aligned.m16n8k16.row.col.f32.f16.f16.f32 "
        "{%0,%1,%2,%3}, {%4,%5,%6,%7}, {%8,%9}, {%0,%1,%2,%3};"
        : "+f"(d[0]), "+f"(d[1]), "+f"(d[2]), "+f"(d[3])
        : "r"(a[0]), "r"(a[1]), "r"(a[2]), "r"(a[3]),
          "r"(b[0]), "r"(b[1]));
}

#define KP 72   // padded smem k stride (halves)

// ------------------------- fp16 warp-MMA GEMM (generic) ----------------------
template<int BN, bool DUAL, bool OUT_HALF>
__global__ void __launch_bounds__(256, 2) mma_gemm_kernel(
    const __half* __restrict__ X0, const __half* __restrict__ X1,
    const __half* __restrict__ W0, const __half* __restrict__ W1,
    const float* __restrict__ b0, const float* __restrict__ b1,
    void* __restrict__ out_v, int n, int fout, int do_relu)
{
    constexpr int NF = BN / 16;
    extern __shared__ __align__(16) __half smem_h[];
    __half* As = smem_h;                     // [2][128*KP]
    __half* Bs = smem_h + 2 * 128 * KP;      // [2][BN*KP]
    float* bias_s = (float*)(smem_h + 2 * 128 * KP + 2 * BN * KP);

    const int tid   = threadIdx.x;
    const int lane  = tid & 31, wid = tid >> 5;
    const int g     = lane >> 2, tig = lane & 3;
    const int m_base = (wid & 3) * 32;
    const int n_base = (wid >> 2) * (BN / 2);
    const int row0  = blockIdx.x * 128;
    const uint32_t sbA = smem_to_u32(smem_h);
    const uint32_t sbB = sbA + 2 * 128 * KP * 2;

    if (tid < BN) {
        float bv = 0.f;
        if (tid < fout) { bv = b0[tid]; if (b1 != nullptr) bv += b1[tid]; }
        bias_s[tid] = bv;
    }

    auto load_chunk = [&](int c, int buf) {
        const __half* X = (c < 2) ? X0 : X1;
        const __half* W = (c < 2) ? W0 : W1;
        const int kc = (c & 1) * 64;
        #pragma unroll
        for (int i = 0; i < 4; i++) {
            int lin = i * 256 + tid;
            int r = lin >> 3, s = lin & 7;
            int gr = row0 + r;
            int ok = (gr < n);
            const __half* src = X + (size_t)(ok ? gr : 0) * 128 + kc + s * 8;
            uint32_t sa = sbA + (uint32_t)(buf * 128 * KP + r * KP + s * 8) * 2;
            CPASYNC16(sa, src, ok ? 16 : 0);
        }
        #pragma unroll
        for (int i = 0; i < BN / 32; i++) {
            int lin = i * 256 + tid;
            int r = lin >> 3, s = lin & 7;
            int ok = (r < fout);
            const __half* src = W + (size_t)(ok ? r : 0) * 128 + kc + s * 8;
            uint32_t sa = sbB + (uint32_t)(buf * BN * KP + r * KP + s * 8) * 2;
            CPASYNC16(sa, src, ok ? 16 : 0);
        }
        CPCOMMIT();
    };

    float acc[2][NF][4];
    #pragma unroll
    for (int mt = 0; mt < 2; mt++)
        #pragma unroll
        for (int f = 0; f < NF; f++)
            #pragma unroll
            for (int j = 0; j < 4; j++) acc[mt][f][j] = 0.f;

    const int nch = DUAL ? 4 : 2;
    load_chunk(0, 0);
    load_chunk(1, 1);

    for (int c = 0; c < nch; c++) {
        if (c + 1 < nch) { CPWAIT(1); } else { CPWAIT(0); }
        __syncthreads();
        const int buf = c & 1;
        const __half* Ab = As + buf * 128 * KP;
        const __half* Bb = Bs + buf * BN * KP;
        #pragma unroll
        for (int kk = 0; kk < 64; kk += 16) {
            uint32_t afr[2][4];
            #pragma unroll
            for (int mt = 0; mt < 2; mt++) {
                int rb = m_base + mt * 16 + g;
                afr[mt][0] = *(const uint32_t*)&Ab[(rb)     * KP + kk + 2 * tig];
                afr[mt][1] = *(const uint32_t*)&Ab[(rb + 8) * KP + kk + 2 * tig];
                afr[mt][2] = *(const uint32_t*)&Ab[(rb)     * KP + kk + 8 + 2 * tig];
                afr[mt][3] = *(const uint32_t*)&Ab[(rb + 8) * KP + kk + 8 + 2 * tig];
            }
            uint32_t bfr[NF][2];
            #pragma unroll
            for (int f = 0; f < NF; f++) {
                int nr = n_base + f * 8 + g;
                bfr[f][0] = *(const uint32_t*)&Bb[nr * KP + kk + 2 * tig];
                bfr[f][1] = *(const uint32_t*)&Bb[nr * KP + kk + 8 + 2 * tig];
            }
            #pragma unroll
            for (int mt = 0; mt < 2; mt++)
                #pragma unroll
                for (int f = 0; f < NF; f++)
                    mma_f16(acc[mt][f], afr[mt], bfr[f]);
        }
        __syncthreads();
        if (c + 2 < nch) load_chunk(c + 2, buf);
    }

    float* outf = (float*)out_v;
    __half* outh = (__half*)out_v;
    #pragma unroll
    for (int mt = 0; mt < 2; mt++) {
        int row = row0 + m_base + mt * 16 + g;
        #pragma unroll
        for (int f = 0; f < NF; f++) {
            int col = n_base + f * 8 + 2 * tig;
            if (col >= fout) continue;
            float bx = bias_s[col], by = bias_s[col + 1];
            float v0 = acc[mt][f][0] + bx, v1 = acc[mt][f][1] + by;
            float v2 = acc[mt][f][2] + bx, v3 = acc[mt][f][3] + by;
            if (do_relu) {
                v0 = fmaxf(v0, 0.f); v1 = fmaxf(v1, 0.f);
                v2 = fmaxf(v2, 0.f); v3 = fmaxf(v3, 0.f);
            }
            if (OUT_HALF) {
                if (row < n)
                    *(__half2*)(outh + (size_t)row * fout + col) = __floats2half2_rn(v0, v1);
                if (row + 8 < n)
                    *(__half2*)(outh + (size_t)(row + 8) * fout + col) = __floats2half2_rn(v2, v3);
            } else {
                if (row < n)
                    *(float2*)(outf + (size_t)row * fout + col) = make_float2(v0, v1);
                if (row + 8 < n)
                    *(float2*)(outf + (size_t)(row + 8) * fout + col) = make_float2(v2, v3);
            }
        }
    }
}

// ------------- fused combine-1 + pool-2 (all dims 128) -----------------------
// Phase 1: h = relu(X0@W0^T + X1@W1^T + b0 + b1)  -> global hh + smem tile
// Phase 2: m = relu(h@W2^T + b2)                  -> global mh
// W2 is prefetched into the B buffers during the last mainloop chunks; the h
// tile is stashed in the A buffers (same [row][KP] chunk layout), so phase 2
// runs entirely from resident smem.
__global__ void __launch_bounds__(256, 2) fused_mid_kernel(
    const __half* __restrict__ X0, const __half* __restrict__ X1,
    const __half* __restrict__ W0, const __half* __restrict__ W1,
    const __half* __restrict__ W2,
    const float* __restrict__ b0, const float* __restrict__ b1,
    const float* __restrict__ b2,
    __half* __restrict__ out_h, __half* __restrict__ out_m, int n)
{
    extern __shared__ __align__(16) __half smem_h[];
    __half* As = smem_h;                     // [2][128*KP]
    __half* Bs = smem_h + 2 * 128 * KP;      // [2][128*KP]
    float* bias_s  = (float*)(smem_h + 4 * 128 * KP);   // [128]
    float* bias2_s = bias_s + 128;                       // [128]

    const int tid   = threadIdx.x;
    const int lane  = tid & 31, wid = tid >> 5;
    const int g     = lane >> 2, tig = lane & 3;
    const int m_base = (wid & 3) * 32;
    const int n_base = (wid >> 2) * 64;
    const int row0  = blockIdx.x * 128;
    const uint32_t sbA = smem_to_u32(smem_h);
    const uint32_t sbB = sbA + 2 * 128 * KP * 2;

    if (tid < 128) {
        bias_s[tid]  = b0[tid] + b1[tid];
        bias2_s[tid] = b2[tid];
    }

    auto load_chunk = [&](int c, int buf) {
        const __half* X = (c < 2) ? X0 : X1;
        const __half* W = (c < 2) ? W0 : W1;
        const int kc = (c & 1) * 64;
        #pragma unroll
        for (int i = 0; i < 4; i++) {
            int lin = i * 256 + tid;
            int r = lin >> 3, s = lin & 7;
            int gr = row0 + r;
            int ok = (gr < n);
            const __half* src = X + (size_t)(ok ? gr : 0) * 128 + kc + s * 8;
            uint32_t sa = sbA + (uint32_t)(buf * 128 * KP + r * KP + s * 8) * 2;
            CPASYNC16(sa, src, ok ? 16 : 0);
        }
        #pragma unroll
        for (int i = 0; i < 4; i++) {
            int lin = i * 256 + tid;
            int r = lin >> 3, s = lin & 7;
            const __half* src = W + (size_t)r * 128 + kc + s * 8;
            uint32_t sa = sbB + (uint32_t)(buf * 128 * KP + r * KP + s * 8) * 2;
            CPASYNC16(sa, src, 16);
        }
        CPCOMMIT();
    };
    // W2 chunk idx (k 64*idx..) into Bs buffer `idx`
    auto load_w2_chunk = [&](int idx) {
        const int kc = idx * 64;
        #pragma unroll
        for (int i = 0; i < 4; i++) {
            int lin = i * 256 + tid;
            int r = lin >> 3, s = lin & 7;
            const __half* src = W2 + (size_t)r * 128 + kc + s * 8;
            uint32_t sa = sbB + (uint32_t)(idx * 128 * KP + r * KP + s * 8) * 2;
            CPASYNC16(sa, src, 16);
        }
        CPCOMMIT();
    };

    float acc[2][8][4];
    auto zero_acc = [&]() {
        #pragma unroll
        for (int mt = 0; mt < 2; mt++)
            #pragma unroll
            for (int f = 0; f < 8; f++)
                #pragma unroll
                for (int j = 0; j < 4; j++) acc[mt][f][j] = 0.f;
    };
    auto compute_chunk = [&](const __half* Ab, const __half* Bb) {
        #pragma unroll
        for (int kk = 0; kk < 64; kk += 16) {
            uint32_t afr[2][4];
            #pragma unroll
            for (int mt = 0; mt < 2; mt++) {
                int rb = m_base + mt * 16 + g;
                afr[mt][0] = *(const uint32_t*)&Ab[(rb)     * KP + kk + 2 * tig];
                afr[mt][1] = *(const uint32_t*)&Ab[(rb + 8) * KP + kk + 2 * tig];
                afr[mt][2] = *(const uint32_t*)&Ab[(rb)     * KP + kk + 8 + 2 * tig];
                afr[mt][3] = *(const uint32_t*)&Ab[(rb + 8) * KP + kk + 8 + 2 * tig];
            }
            uint32_t bfr[8][2];
            #pragma unroll
            for (int f = 0; f < 8; f++) {
                int nr = n_base + f * 8 + g;
                bfr[f][0] = *(const uint32_t*)&Bb[nr * KP + kk + 2 * tig];
                bfr[f][1] = *(const uint32_t*)&Bb[nr * KP + kk + 8 + 2 * tig];
            }
            #pragma unroll
            for (int mt = 0; mt < 2; mt++)
                #pragma unroll
                for (int f = 0; f < 8; f++)
                    mma_f16(acc[mt][f], afr[mt], bfr[f]);
        }
    };

    zero_acc();
    load_chunk(0, 0);
    load_chunk(1, 1);

    // ---- phase 1 mainloop: 4 chunks; tails load next chunk or W2 ----
    #pragma unroll
    for (int c = 0; c < 4; c++) {
        CPWAIT(1);
        __syncthreads();
        const int buf = c & 1;
        compute_chunk(As + buf * 128 * KP, Bs + buf * 128 * KP);
        __syncthreads();
        if (c < 2) load_chunk(c + 2, buf);
        else       load_w2_chunk(c - 2);       // c=2 -> Bs buf0, c=3 -> Bs buf1
    }

    // ---- epilogue 1: h -> global + smem A buffers (chunk layout) ----
    #pragma unroll
    for (int mt = 0; mt < 2; mt++) {
        int lrow = m_base + mt * 16 + g;       // 0..127 (tile row)
        int row  = row0 + lrow;
        #pragma unroll
        for (int f = 0; f < 8; f++) {
            int col = n_base + f * 8 + 2 * tig;
            float bx = bias_s[col], by = bias_s[col + 1];
            float v0 = fmaxf(acc[mt][f][0] + bx, 0.f);
            float v1 = fmaxf(acc[mt][f][1] + by, 0.f);
            float v2 = fmaxf(acc[mt][f][2] + bx, 0.f);
            float v3 = fmaxf(acc[mt][f][3] + by, 0.f);
            __half2 h01 = __floats2half2_rn(v0, v1);
            __half2 h23 = __floats2half2_rn(v2, v3);
            if (row < n)
                *(__half2*)(out_h + (size_t)row * 128 + col) = h01;
            if (row + 8 < n)
                *(__half2*)(out_h + (size_t)(row + 8) * 128 + col) = h23;
            __half* dstA = As + (col >= 64 ? 1 : 0) * 128 * KP;
            int ck = col & 63;
            *(__half2*)&dstA[(lrow)     * KP + ck] = h01;
            *(__half2*)&dstA[(lrow + 8) * KP + ck] = h23;
        }
    }
    CPWAIT(0);                                 // W2 chunks resident
    __syncthreads();                           // h tile visible to all warps

    // ---- phase 2: m = relu(h @ W2^T + b2), fully smem-resident ----
    zero_acc();
    compute_chunk(As, Bs);
    compute_chunk(As + 128 * KP, Bs + 128 * KP);

    #pragma unroll
    for (int mt = 0; mt < 2; mt++) {
        int row = row0 + m_base + mt * 16 + g;
        #pragma unroll
        for (int f = 0; f < 8; f++) {
            int col = n_base + f * 8 + 2 * tig;
            float bx = bias2_s[col], by = bias2_s[col + 1];
            float v0 = fmaxf(acc[mt][f][0] + bx, 0.f);
            float v1 = fmaxf(acc[mt][f][1] + by, 0.f);
            float v2 = fmaxf(acc[mt][f][2] + bx, 0.f);
            float v3 = fmaxf(acc[mt][f][3] + by, 0.f);
            if (row < n)
                *(__half2*)(out_m + (size_t)row * 128 + col) = __floats2half2_rn(v0, v1);
            if (row + 8 < n)
                *(__half2*)(out_m + (size_t)(row + 8) * 128 + col) = __floats2half2_rn(v2, v3);
        }
    }
}

// ------------------------- fused prep: conv_x | conv_w | hist ------------------
#define CXB 12500   // conv_x blocks (NN*FDIM/4/256)
#define CWB 296     // conv_w blocks (75776/256)
#define HB  6250    // hist blocks (NE/256)
__global__ void __launch_bounds__(256) prep_kernel(
    const float4* __restrict__ in_feat, __half2* __restrict__ xh,
    const float* w1, const float* w2, const float* w3,
    const float* w4, const float* w5, const float* w6,
    __half* __restrict__ wh,
    const int* __restrict__ dst, int* __restrict__ deg)
{
    int b = blockIdx.x;
    if (b < CXB) {
        int i = b * 256 + threadIdx.x;
        float4 v = in_feat[i];
        xh[i * 2 + 0] = __floats2half2_rn(v.x, v.y);
        xh[i * 2 + 1] = __floats2half2_rn(v.z, v.w);
    } else if (b < CXB + CWB) {
        int i = (b - CXB) * 256 + threadIdx.x;
        const float* s; int off;
        if      (i < 16384) { s = w1; off = i; }
        else if (i < 32768) { s = w2; off = i - 16384; }
        else if (i < 49152) { s = w3; off = i - 32768; }
        else if (i < 65536) { s = w4; off = i - 49152; }
        else if (i < 70656) { s = w5; off = i - 65536; }
        else if (i < 75776) { s = w6; off = i - 70656; }
        else return;
        wh[i] = __float2half_rn(s[off]);
    } else {
        int e = (b - CXB - CWB) * 256 + threadIdx.x;
        if (e < NE) atomicAdd(&deg[dst[e]], 1);
    }
}

// ------------------------- CSR scan + scatter ----------------------------------
__global__ void __launch_bounds__(1024) scanA_kernel(
    const int* __restrict__ deg, int* __restrict__ off, int* __restrict__ part)
{
    __shared__ int wsum[32];
    const int tid = threadIdx.x, lane = tid & 31, w = tid >> 5;
    int idx = blockIdx.x * 1024 + tid;
    int v = (idx < NN) ? deg[idx] : 0;
    int incl = v;
    #pragma unroll
    for (int d = 1; d < 32; d <<= 1) {
        int t = __shfl_up_sync(~0u, incl, d);
        if (lane >= d) incl += t;
    }
    if (lane == 31) wsum[w] = incl;
    __syncthreads();
    if (w == 0) {
        int s = wsum[lane], si = s;
        #pragma unroll
        for (int d = 1; d < 32; d <<= 1) {
            int t = __shfl_up_sync(~0u, si, d);
            if (lane >= d) si += t;
        }
        wsum[lane] = si - s;
    }
    __syncthreads();
    int excl = incl - v + wsum[w];
    if (idx < NN) off[idx] = excl;
    if (tid == 1023) part[blockIdx.x] = excl + v;
}

__global__ void __launch_bounds__(128) scanB_kernel(int* __restrict__ part,
                                                    int* __restrict__ off, int ntiles)
{
    __shared__ int wsum[4];
    const int tid = threadIdx.x, lane = tid & 31, w = tid >> 5;
    int v = (tid < ntiles) ? part[tid] : 0;
    int incl = v;
    #pragma unroll
    for (int d = 1; d < 32; d <<= 1) {
        int t = __shfl_up_sync(~0u, incl, d);
        if (lane >= d) incl += t;
    }
    if (lane == 31) wsum[w] = incl;
    __syncthreads();
    int woff = 0;
    #pragma unroll
    for (int i = 0; i < 4; i++) if (i < w) woff += wsum[i];
    int excl = incl - v + woff;
    if (tid < ntiles) part[tid] = excl;
    if (tid == 127) off[NN] = excl + v;
}

__global__ void scanC_kernel(int* __restrict__ off, int* __restrict__ pos,
                             const int* __restrict__ part)
{
    int idx = blockIdx.x * 256 + threadIdx.x;
    if (idx < NN) {
        int o = off[idx] + part[idx >> 10];
        off[idx] = o;
        pos[idx] = o;
    }
}

__global__ void scatter_kernel(const int* __restrict__ src, const int* __restrict__ dst,
                               int* __restrict__ pos, int* __restrict__ csr)
{
    int e = blockIdx.x * 256 + threadIdx.x;
    if (e < NE) {
        int p = atomicAdd(&pos[dst[e]], 1);
        csr[p] = src[e];
    }
}

// ------------------------- segment-max via CSR (fp16) --------------------------
__global__ void __launch_bounds__(256) agg_kernel(
    const int* __restrict__ off, const int* __restrict__ csr,
    const __half2* __restrict__ m2, __half2* __restrict__ agg2)
{
    int node = blockIdx.x * 8 + (threadIdx.x >> 5);
    if (node >= NN) return;
    int lane = threadIdx.x & 31;
    int i = off[node], e1 = off[node + 1];
    const int co = lane * 2;
    __half2 mx0 = __float2half2_rn(0.f), mx1 = mx0;
    for (; i + 4 <= e1; i += 4) {
        int s0 = __ldg(&csr[i]),     s1 = __ldg(&csr[i + 1]);
        int s2 = __ldg(&csr[i + 2]), s3 = __ldg(&csr[i + 3]);
        const __half2* p0 = m2 + (size_t)s0 * 64 + co;
        const __half2* p1 = m2 + (size_t)s1 * 64 + co;
        const __half2* p2 = m2 + (size_t)s2 * 64 + co;
        const __half2* p3 = m2 + (size_t)s3 * 64 + co;
        __half2 a0 = p0[0], a1 = p0[1];
        __half2 b0 = p1[0], b1 = p1[1];
        __half2 c0 = p2[0], c1 = p2[1];
        __half2 d0 = p3[0], d1 = p3[1];
        mx0 = __hmax2(mx0, __hmax2(__hmax2(a0, b0), __hmax2(c0, d0)));
        mx1 = __hmax2(mx1, __hmax2(__hmax2(a1, b1), __hmax2(c1, d1)));
    }
    for (; i < e1; i++) {
        int s = __ldg(&csr[i]);
        const __half2* p = m2 + (size_t)s * 64 + co;
        mx0 = __hmax2(mx0, p[0]);
        mx1 = __hmax2(mx1, p[1]);
    }
    agg2[(size_t)node * 64 + co]     = mx0;
    agg2[(size_t)node * 64 + co + 1] = mx1;
}

// ===============================================================================
extern "C" void kernel_launch(void* const* d_in, const int* in_sizes, int n_in,
                              void* d_out, int out_size)
{
    const float* in_feat  = (const float*)d_in[0];
    const int*   src      = (const int*)  d_in[1];
    const int*   dst      = (const int*)  d_in[2];
    const float* pool_w1  = (const float*)d_in[3];
    const float* pool_b1  = (const float*)d_in[4];
    const float* self_w1  = (const float*)d_in[5];
    const float* self_b1  = (const float*)d_in[6];
    const float* neigh_w1 = (const float*)d_in[7];
    const float* neigh_b1 = (const float*)d_in[8];
    const float* pool_w2  = (const float*)d_in[9];
    const float* pool_b2  = (const float*)d_in[10];
    const float* self_w2  = (const float*)d_in[11];
    const float* self_b2  = (const float*)d_in[12];
    const float* neigh_w2 = (const float*)d_in[13];
    const float* neigh_b2 = (const float*)d_in[14];

    __half *mh, *aggh, *hh, *xh, *wh;
    int *deg, *off, *pos, *csr, *part;
    cudaGetSymbolAddress((void**)&mh,   g_mh);
    cudaGetSymbolAddress((void**)&aggh, g_aggh);
    cudaGetSymbolAddress((void**)&hh,   g_hh);
    cudaGetSymbolAddress((void**)&xh,   g_xh);
    cudaGetSymbolAddress((void**)&wh,   g_wh);
    cudaGetSymbolAddress((void**)&deg,  g_deg);
    cudaGetSymbolAddress((void**)&off,  g_off);
    cudaGetSymbolAddress((void**)&pos,  g_pos);
    cudaGetSymbolAddress((void**)&csr,  g_csr);
    cudaGetSymbolAddress((void**)&part, g_part);

    const int ggrid  = (NN + 127) / 128;     // 782
    const int ngrid  = (NN + 7) / 8;
    const int ntiles = (NN + 1023) / 1024;   // 98
    const int pgrid  = CXB + CWB + HB;
    const int SMEM_128  = (2 * 128 * KP + 2 * 128 * KP) * 2 + 128 * 4;   // 74240 B
    const int SMEM_64   = (2 * 128 * KP + 2 * 64 * KP) * 2 + 64 * 4;     // 55552 B
    const int SMEM_FUSE = 4 * 128 * KP * 2 + 256 * 4;                    // 74752 B

    cudaFuncSetAttribute(mma_gemm_kernel<128, false, true>,
                         cudaFuncAttributeMaxDynamicSharedMemorySize, SMEM_128);
    cudaFuncSetAttribute(mma_gemm_kernel<64, true, false>,
                         cudaFuncAttributeMaxDynamicSharedMemorySize, SMEM_64);
    cudaFuncSetAttribute(fused_mid_kernel,
                         cudaFuncAttributeMaxDynamicSharedMemorySize, SMEM_FUSE);

    // ---- prep (fused) + CSR ----
    cudaMemsetAsync(deg, 0, NN * sizeof(int));
    prep_kernel<<<pgrid, 256>>>((const float4*)in_feat, (__half2*)xh,
                                pool_w1, self_w1, neigh_w1, pool_w2, self_w2, neigh_w2,
                                wh, dst, deg);
    scanA_kernel<<<ntiles, 1024>>>(deg, off, part);
    scanB_kernel<<<1, 128>>>(part, off, ntiles);
    scanC_kernel<<<(NN + 255) / 256, 256>>>(off, pos, part);
    scatter_kernel<<<(NE + 255) / 256, 256>>>(src, dst, pos, csr);

    // ---- layer 1 pool ----
    mma_gemm_kernel<128, false, true><<<ggrid, 256, SMEM_128>>>(
        xh, nullptr, wh + WR_PW1, nullptr, pool_b1, nullptr, mh, NN, FDIM, 1);
    agg_kernel<<<ngrid, 256>>>(off, csr, (const __half2*)mh, (__half2*)aggh);

    // ---- fused: combine-1 + pool-2 ----
    fused_mid_kernel<<<ggrid, 256, SMEM_FUSE>>>(
        xh, aggh, wh + WR_SW1, wh + WR_NW1, wh + WR_PW2,
        self_b1, neigh_b1, pool_b2, hh, mh, NN);
    agg_kernel<<<ngrid, 256>>>(off, csr, (const __half2*)mh, (__half2*)aggh);

    // ---- layer 2 combine ----
    mma_gemm_kernel<64, true, false><<<ggrid, 256, SMEM_64>>>(
        hh, aggh, wh + WR_SW2, wh + WR_NW2, self_b2, neigh_b2, (float*)d_out, NN, NCLS, 0);
}